// round 11
// baseline (speedup 1.0000x reference)
#include <cuda_runtime.h>
#include <cuda_bf16.h>
#include <math.h>
#include <stdint.h>

#define B_    2
#define N_    2048
#define D_    512
#define H_    8
#define HD_   64
#define R_    64
#define BAND_ 129
#define BNROWS (B_*N_)     // 4096

// ---------------------------------------------------------------------------
// scratch (static device globals: no allocation)
// ---------------------------------------------------------------------------
__device__ float g_x   [BNROWS * D_];
__device__ float g_rn  [BNROWS];
__device__ float g_qkv [BNROWS * 3 * D_];
__device__ float g_corr[BNROWS * BAND_];
__device__ float g_upd [BNROWS * D_];
__device__ float g_n2  [BNROWS * D_];
__device__ float g_y   [BNROWS * D_];
__device__ float g_h   [BNROWS * 2 * D_];

__device__ __nv_bfloat16 g_act_hi[BNROWS * 2 * D_];   // activation, split-bf16
__device__ __nv_bfloat16 g_act_lo[BNROWS * 2 * D_];

#define OFF_QKV  0
#define OFF_PROJ (1536*512)
#define OFF_M1   (OFF_PROJ + 512*512)
#define OFF_M2   (OFF_M1 + 1024*512)
#define WT_TOTAL (OFF_M2 + 512*1024)
__device__ __nv_bfloat16 g_wt_hi[WT_TOTAL];           // transposed weights [Nc,K]
__device__ __nv_bfloat16 g_wt_lo[WT_TOTAL];

// ---------------------------------------------------------------------------
// baseline-PTX building blocks (NO sm_103a-only instructions)
// ---------------------------------------------------------------------------
__device__ __forceinline__ uint32_t smem_to_u32(const void* p) {
    uint32_t a;
    asm("{ .reg .u64 t; cvta.to.shared.u64 t, %1; cvt.u32.u64 %0, t; }"
        : "=r"(a) : "l"(p));
    return a;
}

__device__ __forceinline__ void cp16(uint32_t dst, const void* src) {
    asm volatile("cp.async.cg.shared.global [%0], [%1], 16;\n"
        :: "r"(dst), "l"(__cvta_generic_to_global(src)) : "memory");
}
__device__ __forceinline__ void cp_commit() {
    asm volatile("cp.async.commit_group;\n" ::: "memory");
}
template<int n> __device__ __forceinline__ void cp_wait() {
    asm volatile("cp.async.wait_group %0;\n" :: "n"(n) : "memory");
}

__device__ __forceinline__ void ldsm_x4(uint32_t (&r)[4], uint32_t addr) {
    asm volatile("ldmatrix.sync.aligned.m8n8.x4.shared.b16 {%0,%1,%2,%3}, [%4];"
        : "=r"(r[0]), "=r"(r[1]), "=r"(r[2]), "=r"(r[3]) : "r"(addr));
}

__device__ __forceinline__ void mma16816(float (&d)[4], const uint32_t (&a)[4],
                                         uint32_t b0, uint32_t b1) {
    asm volatile(
        "mma.sync.aligned.m16n8k16.row.col.f32.bf16.bf16.f32 "
        "{%0,%1,%2,%3}, {%4,%5,%6,%7}, {%8,%9}, {%0,%1,%2,%3};"
        : "+f"(d[0]), "+f"(d[1]), "+f"(d[2]), "+f"(d[3])
        : "r"(a[0]), "r"(a[1]), "r"(a[2]), "r"(a[3]), "r"(b0), "r"(b1));
}

// ---------------------------------------------------------------------------
// GEMM: C[128,128] tile, BK=32, 8 warps (4m x 2n), warp tile 32m x 64n.
// A [M,K] row-major bf16 (hi/lo), B = W^T [Nc,K] row-major bf16 (hi/lo).
// 3-pass split: hi*hi + hi*lo + lo*hi, fp32 accumulate.
// smem rows padded to 80B (stride 20 words -> conflict-free ldmatrix).
// ---------------------------------------------------------------------------
#define LDSB   80
#define MATB   (128 * LDSB)     // 10240 B per matrix tile
#define STAGEB (4 * MATB)       // 40960 B per stage (Ahi,Alo,Bhi,Blo)
#define SMEM_GEMM (2 * STAGEB)  // 81920 B

__device__ __forceinline__ void stage_load(
    uint32_t sbase,
    const __nv_bfloat16* __restrict__ Ahi, const __nv_bfloat16* __restrict__ Alo,
    const __nv_bfloat16* __restrict__ Bhi, const __nv_bfloat16* __restrict__ Blo,
    int aRow0, int bRow0, int K, int kc, int tid)
{
    // 512 granules (16B) per matrix; 256 threads -> 2 per matrix
    #pragma unroll
    for (int g = 0; g < 2; g++) {
        const int idx = g * 256 + tid;
        const int row = idx >> 2;
        const int c16 = idx & 3;
        const uint32_t soff = (uint32_t)row * LDSB + c16 * 16;
        const size_t ao = (size_t)(aRow0 + row) * K + kc + c16 * 8;
        const size_t bo = (size_t)(bRow0 + row) * K + kc + c16 * 8;
        cp16(sbase + 0 * MATB + soff, Ahi + ao);
        cp16(sbase + 1 * MATB + soff, Alo + ao);
        cp16(sbase + 2 * MATB + soff, Bhi + bo);
        cp16(sbase + 3 * MATB + soff, Blo + bo);
    }
}

__device__ __forceinline__ void stage_compute(
    uint32_t sbase, float (&acc)[2][8][4], int wm, int wn, int lane)
{
    // A ldmatrix addressing: lane -> (row, k-group)
    const int rA = lane & 15, gA = lane >> 4;
    // B ldmatrix addressing: x4 covers 2 n-tiles (n0-7 / n8-15) x (k0-7 / k8-15)
    const int grp = lane >> 3, rB = lane & 7;
    const int nof = (grp >> 1) * 8 + rB, kof = (grp & 1) * 8;

    #pragma unroll
    for (int ks = 0; ks < 2; ks++) {
        uint32_t ah[2][4], al[2][4];
        #pragma unroll
        for (int mt = 0; mt < 2; mt++) {
            const uint32_t aaddr = sbase
                + (uint32_t)(wm * 32 + mt * 16 + rA) * LDSB + (ks * 16 + gA * 8) * 2;
            ldsm_x4(ah[mt], aaddr);
            ldsm_x4(al[mt], aaddr + MATB);
        }
        #pragma unroll
        for (int np = 0; np < 4; np++) {
            uint32_t bh[4], bl[4];
            const uint32_t baddr = sbase + 2 * MATB
                + (uint32_t)(wn * 64 + np * 16 + nof) * LDSB + (ks * 16 + kof) * 2;
            ldsm_x4(bh, baddr);
            ldsm_x4(bl, baddr + MATB);
            #pragma unroll
            for (int mt = 0; mt < 2; mt++) {
                #pragma unroll
                for (int hn = 0; hn < 2; hn++) {
                    float (&d)[4] = acc[mt][np * 2 + hn];
                    mma16816(d, ah[mt], bh[hn * 2], bh[hn * 2 + 1]);
                    mma16816(d, ah[mt], bl[hn * 2], bl[hn * 2 + 1]);
                    mma16816(d, al[mt], bh[hn * 2], bh[hn * 2 + 1]);
                }
            }
        }
    }
}

__device__ __forceinline__ void run_gemm(
    char* smem_c, float (&acc)[2][8][4],
    const __nv_bfloat16* Ahi, const __nv_bfloat16* Alo,
    const __nv_bfloat16* Bhi, const __nv_bfloat16* Blo,
    int aRow0, int bRow0, int K)
{
    const uint32_t sb = smem_to_u32(smem_c);
    const int tid = threadIdx.x;
    const int wid = tid >> 5, lane = tid & 31;
    const int wm = wid & 3, wn = wid >> 2;

    #pragma unroll
    for (int i = 0; i < 2; i++)
        #pragma unroll
        for (int j = 0; j < 8; j++)
            #pragma unroll
            for (int k = 0; k < 4; k++) acc[i][j][k] = 0.f;

    const int nit = K / 32;
    stage_load(sb, Ahi, Alo, Bhi, Blo, aRow0, bRow0, K, 0, tid);
    cp_commit();
    for (int it = 0; it < nit; it++) {
        if (it + 1 < nit) {
            stage_load(sb + ((it + 1) & 1) * STAGEB, Ahi, Alo, Bhi, Blo,
                       aRow0, bRow0, K, (it + 1) * 32, tid);
            cp_commit();
            cp_wait<1>();
        } else {
            cp_wait<0>();
        }
        __syncthreads();
        stage_compute(sb + (it & 1) * STAGEB, acc, wm, wn, lane);
        __syncthreads();
    }
}

// EPI: 0 = +bias, 1 = +bias+residual, 2 = +bias+exact gelu
template<int EPI>
__global__ void __launch_bounds__(256, 2) mma_gemm(
    const __nv_bfloat16* __restrict__ Ahi, const __nv_bfloat16* __restrict__ Alo,
    const __nv_bfloat16* __restrict__ Bhi, const __nv_bfloat16* __restrict__ Blo,
    const float* __restrict__ bias, const float* __restrict__ res,
    float* __restrict__ C, int M, int Nc, int K)
{
    extern __shared__ char smem[];
    float acc[2][8][4];
    const int m0 = blockIdx.y * 128, n0 = blockIdx.x * 128;
    run_gemm(smem, acc, Ahi, Alo, Bhi, Blo, m0, n0, K);

    const int wid = threadIdx.x >> 5, lane = threadIdx.x & 31;
    const int wm = wid & 3, wn = wid >> 2;
    const int g = lane >> 2, tg = lane & 3;

    #pragma unroll
    for (int nt = 0; nt < 8; nt++) {
        const int col = n0 + wn * 64 + nt * 8 + 2 * tg;
        const float b0 = bias[col], b1 = bias[col + 1];
        #pragma unroll
        for (int mt = 0; mt < 2; mt++) {
            #pragma unroll
            for (int hr = 0; hr < 2; hr++) {
                const int row = m0 + wm * 32 + mt * 16 + g + hr * 8;
                float vx = acc[mt][nt][hr * 2 + 0] + b0;
                float vy = acc[mt][nt][hr * 2 + 1] + b1;
                if (EPI == 1) {
                    const float2 r2 = *(const float2*)(res + (size_t)row * Nc + col);
                    vx += r2.x; vy += r2.y;
                } else if (EPI == 2) {
                    vx = 0.5f * vx * (1.0f + erff(vx * 0.70710678118654752f));
                    vy = 0.5f * vy * (1.0f + erff(vy * 0.70710678118654752f));
                }
                float2 o; o.x = vx; o.y = vy;
                *(float2*)(C + (size_t)row * Nc + col) = o;
            }
        }
    }
}

// banded correlation via HMMA: X@X^T on diagonal-adjacent 128x128 tiles
__global__ void __launch_bounds__(256, 2) mma_corr(
    const __nv_bfloat16* __restrict__ Xhi, const __nv_bfloat16* __restrict__ Xlo,
    const float* __restrict__ rn, float* __restrict__ corrT)
{
    const int b  = blockIdx.y;
    const int bi = blockIdx.x / 3;
    const int bj = bi + (blockIdx.x % 3) - 1;
    if (bj < 0 || bj >= N_ / 128) return;

    extern __shared__ char smem[];
    float acc[2][8][4];
    const int m0 = bi * 128, n0 = bj * 128;
    run_gemm(smem, acc, Xhi, Xlo, Xhi, Xlo, b * N_ + m0, b * N_ + n0, D_);

    const int wid = threadIdx.x >> 5, lane = threadIdx.x & 31;
    const int wm = wid & 3, wn = wid >> 2;
    const int g = lane >> 2, tg = lane & 3;

    #pragma unroll
    for (int mt = 0; mt < 2; mt++) {
        #pragma unroll
        for (int hr = 0; hr < 2; hr++) {
            const int gi = m0 + wm * 32 + mt * 16 + g + hr * 8;
            const float rni = rn[b * N_ + gi];
            #pragma unroll
            for (int nt = 0; nt < 8; nt++) {
                #pragma unroll
                for (int cc = 0; cc < 2; cc++) {
                    const int gj = n0 + wn * 64 + nt * 8 + 2 * tg + cc;
                    const int r = gi - gj;
                    if (r >= -R_ && r <= R_)
                        corrT[(size_t)(b * N_ + gj) * BAND_ + (r + R_)] =
                            acc[mt][nt][hr * 2 + cc] * rni * rn[b * N_ + gj];
                }
            }
        }
    }
}

// ---------------------------------------------------------------------------
// LayerNorm (+ optional rep inverse-norm)
// ---------------------------------------------------------------------------
__global__ void __launch_bounds__(128) ln_kernel(
    const float* __restrict__ in, const float* __restrict__ gam,
    const float* __restrict__ bet, float* __restrict__ out,
    float* __restrict__ rnorm)
{
    const int row = blockIdx.x;
    const int t = threadIdx.x;
    const float4 v = ((const float4*)(in + (size_t)row * D_))[t];

    float s  = v.x + v.y + v.z + v.w;
    float ss = v.x*v.x + v.y*v.y + v.z*v.z + v.w*v.w;
    __shared__ float redA[4], redB[4], redC[4];
    #pragma unroll
    for (int o = 16; o > 0; o >>= 1) {
        s  += __shfl_xor_sync(0xffffffffu, s,  o);
        ss += __shfl_xor_sync(0xffffffffu, ss, o);
    }
    const int w = t >> 5;
    if ((t & 31) == 0) { redA[w] = s; redB[w] = ss; }
    __syncthreads();
    s  = redA[0] + redA[1] + redA[2] + redA[3];
    ss = redB[0] + redB[1] + redB[2] + redB[3];

    const float mean = s * (1.0f / D_);
    const float var  = ss * (1.0f / D_) - mean * mean;
    const float rstd = rsqrtf(var + 1e-5f);

    const float4 gv = ((const float4*)gam)[t];
    const float4 bv = ((const float4*)bet)[t];
    float4 xo;
    xo.x = (v.x - mean) * rstd * gv.x + bv.x;
    xo.y = (v.y - mean) * rstd * gv.y + bv.y;
    xo.z = (v.z - mean) * rstd * gv.z + bv.z;
    xo.w = (v.w - mean) * rstd * gv.w + bv.w;
    ((float4*)(out + (size_t)row * D_))[t] = xo;

    if (rnorm != nullptr) {
        float q = xo.x*xo.x + xo.y*xo.y + xo.z*xo.z + xo.w*xo.w;
        #pragma unroll
        for (int o = 16; o > 0; o >>= 1) q += __shfl_xor_sync(0xffffffffu, q, o);
        if ((t & 31) == 0) redC[w] = q;
        __syncthreads();
        if (t == 0) {
            float tot = redC[0] + redC[1] + redC[2] + redC[3];
            rnorm[row] = 1.0f / fmaxf(sqrtf(tot), 1e-12f);
        }
    }
}

// ---------------------------------------------------------------------------
// fp32 -> split-bf16 (hi + lo) elementwise
// ---------------------------------------------------------------------------
__global__ void __launch_bounds__(256) cvt_k(
    const float* __restrict__ in, __nv_bfloat16* __restrict__ hi,
    __nv_bfloat16* __restrict__ lo, int n4)
{
    const int idx = blockIdx.x * 256 + threadIdx.x;
    if (idx >= n4) return;
    const float4 v = ((const float4*)in)[idx];
    const __nv_bfloat16 hx = __float2bfloat16(v.x);
    const __nv_bfloat16 hy = __float2bfloat16(v.y);
    const __nv_bfloat16 hz = __float2bfloat16(v.z);
    const __nv_bfloat16 hw = __float2bfloat16(v.w);
    __nv_bfloat162 h0; h0.x = hx; h0.y = hy;
    __nv_bfloat162 h1; h1.x = hz; h1.y = hw;
    __nv_bfloat162 l0, l1;
    l0.x = __float2bfloat16(v.x - __bfloat162float(hx));
    l0.y = __float2bfloat16(v.y - __bfloat162float(hy));
    l1.x = __float2bfloat16(v.z - __bfloat162float(hz));
    l1.y = __float2bfloat16(v.w - __bfloat162float(hw));
    ((__nv_bfloat162*)hi)[2*idx]   = h0;
    ((__nv_bfloat162*)hi)[2*idx+1] = h1;
    ((__nv_bfloat162*)lo)[2*idx]   = l0;
    ((__nv_bfloat162*)lo)[2*idx+1] = l1;
}

// weight transpose + split: W [K,Nc] fp32 -> T [Nc,K] bf16 hi/lo
__global__ void __launch_bounds__(256) wtr_k(
    const float* __restrict__ W, __nv_bfloat16* __restrict__ Thi,
    __nv_bfloat16* __restrict__ Tlo, int K, int Nc)
{
    __shared__ float tile[32][33];
    const int n0 = blockIdx.x * 32, k0 = blockIdx.y * 32;
    const int tx = threadIdx.x & 31, ty = threadIdx.x >> 5;   // 32x8
    #pragma unroll
    for (int r = 0; r < 32; r += 8)
        tile[ty + r][tx] = W[(size_t)(k0 + ty + r) * Nc + n0 + tx];
    __syncthreads();
    #pragma unroll
    for (int r = 0; r < 32; r += 8) {
        const float v = tile[tx][ty + r];
        const __nv_bfloat16 h = __float2bfloat16(v);
        const size_t o = (size_t)(n0 + ty + r) * K + k0 + tx;
        Thi[o] = h;
        Tlo[o] = __float2bfloat16(v - __bfloat162float(h));
    }
}

// ---------------------------------------------------------------------------
// banded attention: 2 threads per query (split head-dim), 256 thr / 128 queries
// out-of-band keys use sentinel -1e30 with m init -1e29 so exp underflows to 0
// ---------------------------------------------------------------------------
__global__ void __launch_bounds__(256) attn_k(
    const float* __restrict__ qkv, const float* __restrict__ corrT,
    const float* __restrict__ rel_bias, const float* __restrict__ rep_scale,
    float* __restrict__ upd)
{
    const int qt = blockIdx.x, h = blockIdx.y, b = blockIdx.z;
    const int q0 = qt * 128;
    const int t  = threadIdx.x;
    const int qi = t >> 1;          // query within tile
    const int hf = t & 1;           // head-dim half
    const int i  = q0 + qi;
    const float rs = rep_scale[h];

    __shared__ float Ks[64][64];
    __shared__ float Vs[64][64];
    __shared__ float bias_s[BAND_];
    for (int r = t; r < BAND_; r += 256)
        bias_s[r] = rel_bias[(size_t)(r - R_ + N_ - 1) * H_ + h];

    float4 q4[8];
    const float4* qp = (const float4*)(qkv + (size_t)(b * N_ + i) * (3 * D_)
                                       + h * HD_ + hf * 32);
    #pragma unroll
    for (int c = 0; c < 8; c++) q4[c] = qp[c];

    float m = -1e29f, l = 0.f;
    float4 a4[8];
    #pragma unroll
    for (int c = 0; c < 8; c++) a4[c] = make_float4(0.f, 0.f, 0.f, 0.f);

    const int j0 = q0 - 64;
    const int w = t >> 5;
    const int iw0 = q0 + w * 16;                    // warp covers 16 queries
    const int jlo = max(0, iw0 - R_);
    const int jhi = min(N_ - 1, iw0 + 15 + R_);

    for (int cch = 0; cch < 4; cch++) {
        const int cbase = j0 + cch * 64;
        __syncthreads();
        for (int idx = t; idx < 64 * 16; idx += 256) {
            const int rrow = idx >> 4, c4 = idx & 15;
            const int j = cbase + rrow;
            float4 kv = make_float4(0.f, 0.f, 0.f, 0.f), vv = kv;
            if (j >= 0 && j < N_) {
                const float* base = qkv + (size_t)(b * N_ + j) * (3 * D_) + h * HD_;
                kv = *(const float4*)(base + D_     + c4 * 4);
                vv = *(const float4*)(base + 2 * D_ + c4 * 4);
            }
            ((float4*)&Ks[0][0])[idx] = kv;
            ((float4*)&Vs[0][0])[idx] = vv;
        }
        __syncthreads();

        const int lo = max(jlo, cbase), hi = min(jhi, cbase + 63);
        for (int jj = lo; jj <= hi; jj++) {
            const int kr = jj - cbase;
            const float4* kp = (const float4*)&Ks[kr][hf * 32];
            float s = 0.f;
            #pragma unroll
            for (int c = 0; c < 8; c++) {
                s = fmaf(q4[c].x, kp[c].x, s);
                s = fmaf(q4[c].y, kp[c].y, s);
                s = fmaf(q4[c].z, kp[c].z, s);
                s = fmaf(q4[c].w, kp[c].w, s);
            }
            s += __shfl_xor_sync(0xffffffffu, s, 1);    // combine dim halves
            const int r = i - jj;
            const int rc = min(max(r, -R_), R_);
            const float sv = s * 0.125f
                + corrT[(size_t)(b * N_ + jj) * BAND_ + rc + R_] * rs
                + bias_s[rc + R_];
            s = (r >= -R_ && r <= R_) ? sv : -1e30f;

            const float mn = fmaxf(m, s);
            if (mn > m) {
                const float sc = __expf(m - mn);
                l *= sc;
                #pragma unroll
                for (int c = 0; c < 8; c++) {
                    a4[c].x *= sc; a4[c].y *= sc; a4[c].z *= sc; a4[c].w *= sc;
                }
                m = mn;
            }
            const float p = __expf(s - m);
            l += p;
            const float4* vp = (const float4*)&Vs[kr][hf * 32];
            #pragma unroll
            for (int c = 0; c < 8; c++) {
                a4[c].x = fmaf(p, vp[c].x, a4[c].x);
                a4[c].y = fmaf(p, vp[c].y, a4[c].y);
                a4[c].z = fmaf(p, vp[c].z, a4[c].z);
                a4[c].w = fmaf(p, vp[c].w, a4[c].w);
            }
        }
    }

    const float inv = 1.0f / l;
    float4* op = (float4*)(upd + (size_t)(b * N_ + i) * D_ + h * HD_ + hf * 32);
    #pragma unroll
    for (int c = 0; c < 8; c++) {
        float4 o;
        o.x = a4[c].x * inv; o.y = a4[c].y * inv;
        o.z = a4[c].z * inv; o.w = a4[c].w * inv;
        op[c] = o;
    }
}

// ---------------------------------------------------------------------------
// launcher
// ---------------------------------------------------------------------------
extern "C" void kernel_launch(void* const* d_in, const int* in_sizes, int n_in,
                              void* d_out, int out_size)
{
    const float* nodes  = (const float*)d_in[0];
    const float* ln1_g  = (const float*)d_in[1];
    const float* ln1_b  = (const float*)d_in[2];
    const float* qkv_w  = (const float*)d_in[3];
    const float* qkv_b  = (const float*)d_in[4];
    const float* proj_w = (const float*)d_in[5];
    const float* proj_b = (const float*)d_in[6];
    const float* rep_s  = (const float*)d_in[7];
    const float* rel_b  = (const float*)d_in[8];
    const float* ln2_g  = (const float*)d_in[9];
    const float* ln2_b  = (const float*)d_in[10];
    const float* mlp_w1 = (const float*)d_in[11];
    const float* mlp_b1 = (const float*)d_in[12];
    const float* mlp_w2 = (const float*)d_in[13];
    const float* mlp_b2 = (const float*)d_in[14];
    float* out = (float*)d_out;

    float *x, *rn, *qkv, *corr, *upd, *n2, *y, *hb;
    __nv_bfloat16 *ahi, *alo, *whi, *wlo;
    cudaGetSymbolAddress((void**)&x,    g_x);
    cudaGetSymbolAddress((void**)&rn,   g_rn);
    cudaGetSymbolAddress((void**)&qkv,  g_qkv);
    cudaGetSymbolAddress((void**)&corr, g_corr);
    cudaGetSymbolAddress((void**)&upd,  g_upd);
    cudaGetSymbolAddress((void**)&n2,   g_n2);
    cudaGetSymbolAddress((void**)&y,    g_y);
    cudaGetSymbolAddress((void**)&hb,   g_h);
    cudaGetSymbolAddress((void**)&ahi,  g_act_hi);
    cudaGetSymbolAddress((void**)&alo,  g_act_lo);
    cudaGetSymbolAddress((void**)&whi,  g_wt_hi);
    cudaGetSymbolAddress((void**)&wlo,  g_wt_lo);

    cudaFuncSetAttribute(mma_gemm<0>, cudaFuncAttributeMaxDynamicSharedMemorySize, SMEM_GEMM);
    cudaFuncSetAttribute(mma_gemm<1>, cudaFuncAttributeMaxDynamicSharedMemorySize, SMEM_GEMM);
    cudaFuncSetAttribute(mma_gemm<2>, cudaFuncAttributeMaxDynamicSharedMemorySize, SMEM_GEMM);
    cudaFuncSetAttribute(mma_corr,    cudaFuncAttributeMaxDynamicSharedMemorySize, SMEM_GEMM);

    // weight transposes + split (deterministic each call)
    wtr_k<<<dim3(48, 16), 256>>>(qkv_w,  whi + OFF_QKV,  wlo + OFF_QKV,  512, 1536);
    wtr_k<<<dim3(16, 16), 256>>>(proj_w, whi + OFF_PROJ, wlo + OFF_PROJ, 512, 512);
    wtr_k<<<dim3(32, 16), 256>>>(mlp_w1, whi + OFF_M1,   wlo + OFF_M1,   512, 1024);
    wtr_k<<<dim3(16, 32), 256>>>(mlp_w2, whi + OFF_M2,   wlo + OFF_M2,   1024, 512);

    // 1) LN1 + rep inverse-norm
    ln_kernel<<<BNROWS, 128>>>(nodes, ln1_g, ln1_b, x, rn);
    // 2) x -> split bf16
    cvt_k<<<(BNROWS * D_ / 4 + 255) / 256, 256>>>(x, ahi, alo, BNROWS * D_ / 4);
    // 3) QKV projection
    mma_gemm<0><<<dim3(12, 32), 256, SMEM_GEMM>>>(
        ahi, alo, whi + OFF_QKV, wlo + OFF_QKV, qkv_b, nullptr, qkv,
        BNROWS, 3 * D_, D_);
    // 4) banded correlation (HMMA on X@X^T diagonal tiles)
    mma_corr<<<dim3(48, B_), 256, SMEM_GEMM>>>(ahi, alo, rn, corr);
    // 5) banded attention
    attn_k<<<dim3(N_ / 128, H_, B_), 256>>>(qkv, corr, rel_b, rep_s, upd);
    // 6) upd -> split bf16; output projection + residual
    cvt_k<<<(BNROWS * D_ / 4 + 255) / 256, 256>>>(upd, ahi, alo, BNROWS * D_ / 4);
    mma_gemm<1><<<dim3(4, 32), 256, SMEM_GEMM>>>(
        ahi, alo, whi + OFF_PROJ, wlo + OFF_PROJ, proj_b, nodes, n2,
        BNROWS, D_, D_);
    // 7) LN2
    ln_kernel<<<BNROWS, 128>>>(n2, ln2_g, ln2_b, y, nullptr);
    // 8) MLP up + gelu
    cvt_k<<<(BNROWS * D_ / 4 + 255) / 256, 256>>>(y, ahi, alo, BNROWS * D_ / 4);
    mma_gemm<2><<<dim3(8, 32), 256, SMEM_GEMM>>>(
        ahi, alo, whi + OFF_M1, wlo + OFF_M1, mlp_b1, nullptr, hb,
        BNROWS, 2 * D_, D_);
    // 9) MLP down + residual -> out
    cvt_k<<<(BNROWS * 2 * D_ / 4 + 255) / 256, 256>>>(hb, ahi, alo, BNROWS * 2 * D_ / 4);
    mma_gemm<1><<<dim3(4, 32), 256, SMEM_GEMM>>>(
        ahi, alo, whi + OFF_M2, wlo + OFF_M2, mlp_b2, n2, out,
        BNROWS, D_, 2 * D_);
}

// round 13
// speedup vs baseline: 1.0580x; 1.0580x over previous
#include <cuda_runtime.h>
#include <cuda_bf16.h>
#include <math.h>
#include <stdint.h>

#define B_    2
#define N_    2048
#define D_    512
#define H_    8
#define HD_   64
#define R_    64
#define BAND_ 129
#define BNROWS (B_*N_)     // 4096

// ---------------------------------------------------------------------------
// scratch (static device globals: no allocation)
// ---------------------------------------------------------------------------
__device__ float g_rn  [BNROWS];
__device__ float g_qkv [BNROWS * 3 * D_];
__device__ float g_corr[BNROWS * BAND_];
__device__ float g_n2  [BNROWS * D_];

// activation split-bf16 planes. Layout:
//   [0 .. BNROWS*D_)              : current 512-wide activation (x / upd / y)
//   [BNROWS*D_ .. BNROWS*3*D_)    : 1024-wide gelu output hb
__device__ __nv_bfloat16 g_act_hi[BNROWS * 3 * D_];
__device__ __nv_bfloat16 g_act_lo[BNROWS * 3 * D_];

#define OFF_QKV  0
#define OFF_PROJ (1536*512)
#define OFF_M1   (OFF_PROJ + 512*512)
#define OFF_M2   (OFF_M1 + 1024*512)
#define WT_TOTAL (OFF_M2 + 512*1024)
__device__ __nv_bfloat16 g_wt_hi[WT_TOTAL];           // transposed weights [Nc,K]
__device__ __nv_bfloat16 g_wt_lo[WT_TOTAL];

// ---------------------------------------------------------------------------
// baseline-PTX building blocks (NO sm_103a-only instructions)
// ---------------------------------------------------------------------------
__device__ __forceinline__ uint32_t smem_to_u32(const void* p) {
    uint32_t a;
    asm("{ .reg .u64 t; cvta.to.shared.u64 t, %1; cvt.u32.u64 %0, t; }"
        : "=r"(a) : "l"(p));
    return a;
}

__device__ __forceinline__ void cp16(uint32_t dst, const void* src) {
    asm volatile("cp.async.cg.shared.global [%0], [%1], 16;\n"
        :: "r"(dst), "l"(__cvta_generic_to_global(src)) : "memory");
}
__device__ __forceinline__ void cp_commit() {
    asm volatile("cp.async.commit_group;\n" ::: "memory");
}
template<int n> __device__ __forceinline__ void cp_wait() {
    asm volatile("cp.async.wait_group %0;\n" :: "n"(n) : "memory");
}

__device__ __forceinline__ void ldsm_x4(uint32_t (&r)[4], uint32_t addr) {
    asm volatile("ldmatrix.sync.aligned.m8n8.x4.shared.b16 {%0,%1,%2,%3}, [%4];"
        : "=r"(r[0]), "=r"(r[1]), "=r"(r[2]), "=r"(r[3]) : "r"(addr));
}

__device__ __forceinline__ void mma16816(float (&d)[4], const uint32_t (&a)[4],
                                         uint32_t b0, uint32_t b1) {
    asm volatile(
        "mma.sync.aligned.m16n8k16.row.col.f32.bf16.bf16.f32 "
        "{%0,%1,%2,%3}, {%4,%5,%6,%7}, {%8,%9}, {%0,%1,%2,%3};"
        : "+f"(d[0]), "+f"(d[1]), "+f"(d[2]), "+f"(d[3])
        : "r"(a[0]), "r"(a[1]), "r"(a[2]), "r"(a[3]), "r"(b0), "r"(b1));
}

__device__ __forceinline__ void split_bf16(float v, __nv_bfloat16& h, __nv_bfloat16& l) {
    h = __float2bfloat16(v);
    l = __float2bfloat16(v - __bfloat162float(h));
}

// ---------------------------------------------------------------------------
// GEMM: C[128,128] tile, BK=32, 8 warps (4m x 2n), warp tile 32m x 64n.
// A [M,K] row-major bf16 (hi/lo), B = W^T [Nc,K] row-major bf16 (hi/lo).
// 3-pass split: hi*hi + hi*lo + lo*hi, fp32 accumulate.
// smem rows padded to 80B (stride 20 words -> conflict-free ldmatrix).
// ---------------------------------------------------------------------------
#define LDSB   80
#define MATB   (128 * LDSB)     // 10240 B per matrix tile
#define STAGEB (4 * MATB)       // 40960 B per stage (Ahi,Alo,Bhi,Blo)
#define SMEM_GEMM (2 * STAGEB)  // 81920 B

__device__ __forceinline__ void stage_load(
    uint32_t sbase,
    const __nv_bfloat16* __restrict__ Ahi, const __nv_bfloat16* __restrict__ Alo,
    const __nv_bfloat16* __restrict__ Bhi, const __nv_bfloat16* __restrict__ Blo,
    int aRow0, int bRow0, int K, int kc, int tid)
{
    #pragma unroll
    for (int g = 0; g < 2; g++) {
        const int idx = g * 256 + tid;
        const int row = idx >> 2;
        const int c16 = idx & 3;
        const uint32_t soff = (uint32_t)row * LDSB + c16 * 16;
        const size_t ao = (size_t)(aRow0 + row) * K + kc + c16 * 8;
        const size_t bo = (size_t)(bRow0 + row) * K + kc + c16 * 8;
        cp16(sbase + 0 * MATB + soff, Ahi + ao);
        cp16(sbase + 1 * MATB + soff, Alo + ao);
        cp16(sbase + 2 * MATB + soff, Bhi + bo);
        cp16(sbase + 3 * MATB + soff, Blo + bo);
    }
}

__device__ __forceinline__ void stage_compute(
    uint32_t sbase, float (&acc)[2][8][4], int wm, int wn, int lane)
{
    const int rA = lane & 15, gA = lane >> 4;
    const int grp = lane >> 3, rB = lane & 7;
    const int nof = (grp >> 1) * 8 + rB, kof = (grp & 1) * 8;

    #pragma unroll
    for (int ks = 0; ks < 2; ks++) {
        uint32_t ah[2][4], al[2][4];
        #pragma unroll
        for (int mt = 0; mt < 2; mt++) {
            const uint32_t aaddr = sbase
                + (uint32_t)(wm * 32 + mt * 16 + rA) * LDSB + (ks * 16 + gA * 8) * 2;
            ldsm_x4(ah[mt], aaddr);
            ldsm_x4(al[mt], aaddr + MATB);
        }
        #pragma unroll
        for (int np = 0; np < 4; np++) {
            uint32_t bh[4], bl[4];
            const uint32_t baddr = sbase + 2 * MATB
                + (uint32_t)(wn * 64 + np * 16 + nof) * LDSB + (ks * 16 + kof) * 2;
            ldsm_x4(bh, baddr);
            ldsm_x4(bl, baddr + MATB);
            #pragma unroll
            for (int mt = 0; mt < 2; mt++) {
                #pragma unroll
                for (int hn = 0; hn < 2; hn++) {
                    float (&d)[4] = acc[mt][np * 2 + hn];
                    mma16816(d, ah[mt], bh[hn * 2], bh[hn * 2 + 1]);
                    mma16816(d, ah[mt], bl[hn * 2], bl[hn * 2 + 1]);
                    mma16816(d, al[mt], bh[hn * 2], bh[hn * 2 + 1]);
                }
            }
        }
    }
}

__device__ __forceinline__ void run_gemm(
    char* smem_c, float (&acc)[2][8][4],
    const __nv_bfloat16* Ahi, const __nv_bfloat16* Alo,
    const __nv_bfloat16* Bhi, const __nv_bfloat16* Blo,
    int aRow0, int bRow0, int K)
{
    const uint32_t sb = smem_to_u32(smem_c);
    const int tid = threadIdx.x;
    const int wid = tid >> 5, lane = tid & 31;
    const int wm = wid & 3, wn = wid >> 2;

    #pragma unroll
    for (int i = 0; i < 2; i++)
        #pragma unroll
        for (int j = 0; j < 8; j++)
            #pragma unroll
            for (int k = 0; k < 4; k++) acc[i][j][k] = 0.f;

    const int nit = K / 32;
    stage_load(sb, Ahi, Alo, Bhi, Blo, aRow0, bRow0, K, 0, tid);
    cp_commit();
    for (int it = 0; it < nit; it++) {
        if (it + 1 < nit) {
            stage_load(sb + ((it + 1) & 1) * STAGEB, Ahi, Alo, Bhi, Blo,
                       aRow0, bRow0, K, (it + 1) * 32, tid);
            cp_commit();
            cp_wait<1>();
        } else {
            cp_wait<0>();
        }
        __syncthreads();
        stage_compute(sb + (it & 1) * STAGEB, acc, wm, wn, lane);
        __syncthreads();
    }
}

// EPI: 0 = +bias -> fp32 C
//      1 = +bias+residual -> fp32 C
//      2 = +bias+exact gelu -> split-bf16 (Chi/Clo)
template<int EPI>
__global__ void __launch_bounds__(256, 2) mma_gemm(
    const __nv_bfloat16* __restrict__ Ahi, const __nv_bfloat16* __restrict__ Alo,
    const __nv_bfloat16* __restrict__ Bhi, const __nv_bfloat16* __restrict__ Blo,
    const float* __restrict__ bias, const float* __restrict__ res,
    float* __restrict__ C, __nv_bfloat16* __restrict__ Chi,
    __nv_bfloat16* __restrict__ Clo, int M, int Nc, int K)
{
    extern __shared__ char smem[];
    float acc[2][8][4];
    const int m0 = blockIdx.y * 128, n0 = blockIdx.x * 128;
    run_gemm(smem, acc, Ahi, Alo, Bhi, Blo, m0, n0, K);

    const int wid = threadIdx.x >> 5, lane = threadIdx.x & 31;
    const int wm = wid & 3, wn = wid >> 2;
    const int g = lane >> 2, tg = lane & 3;

    #pragma unroll
    for (int nt = 0; nt < 8; nt++) {
        const int col = n0 + wn * 64 + nt * 8 + 2 * tg;
        const float b0 = bias[col], b1 = bias[col + 1];
        #pragma unroll
        for (int mt = 0; mt < 2; mt++) {
            #pragma unroll
            for (int hr = 0; hr < 2; hr++) {
                const int row = m0 + wm * 32 + mt * 16 + g + hr * 8;
                float vx = acc[mt][nt][hr * 2 + 0] + b0;
                float vy = acc[mt][nt][hr * 2 + 1] + b1;
                if (EPI == 1) {
                    const float2 r2 = *(const float2*)(res + (size_t)row * Nc + col);
                    vx += r2.x; vy += r2.y;
                    float2 o; o.x = vx; o.y = vy;
                    *(float2*)(C + (size_t)row * Nc + col) = o;
                } else if (EPI == 2) {
                    vx = 0.5f * vx * (1.0f + erff(vx * 0.70710678118654752f));
                    vy = 0.5f * vy * (1.0f + erff(vy * 0.70710678118654752f));
                    __nv_bfloat162 h2, l2;
                    split_bf16(vx, h2.x, l2.x);
                    split_bf16(vy, h2.y, l2.y);
                    *(__nv_bfloat162*)(Chi + (size_t)row * Nc + col) = h2;
                    *(__nv_bfloat162*)(Clo + (size_t)row * Nc + col) = l2;
                } else {
                    float2 o; o.x = vx; o.y = vy;
                    *(float2*)(C + (size_t)row * Nc + col) = o;
                }
            }
        }
    }
}

// banded correlation via HMMA: X@X^T on diagonal-adjacent 128x128 tiles
__global__ void __launch_bounds__(256, 2) mma_corr(
    const __nv_bfloat16* __restrict__ Xhi, const __nv_bfloat16* __restrict__ Xlo,
    const float* __restrict__ rn, float* __restrict__ corrT)
{
    const int b  = blockIdx.y;
    const int bi = blockIdx.x / 3;
    const int bj = bi + (blockIdx.x % 3) - 1;
    if (bj < 0 || bj >= N_ / 128) return;

    extern __shared__ char smem[];
    float acc[2][8][4];
    const int m0 = bi * 128, n0 = bj * 128;
    run_gemm(smem, acc, Xhi, Xlo, Xhi, Xlo, b * N_ + m0, b * N_ + n0, D_);

    const int wid = threadIdx.x >> 5, lane = threadIdx.x & 31;
    const int wm = wid & 3, wn = wid >> 2;
    const int g = lane >> 2, tg = lane & 3;

    #pragma unroll
    for (int mt = 0; mt < 2; mt++) {
        #pragma unroll
        for (int hr = 0; hr < 2; hr++) {
            const int gi = m0 + wm * 32 + mt * 16 + g + hr * 8;
            const float rni = rn[b * N_ + gi];
            #pragma unroll
            for (int nt = 0; nt < 8; nt++) {
                #pragma unroll
                for (int cc = 0; cc < 2; cc++) {
                    const int gj = n0 + wn * 64 + nt * 8 + 2 * tg + cc;
                    const int r = gi - gj;
                    if (r >= -R_ && r <= R_)
                        corrT[(size_t)(b * N_ + gj) * BAND_ + (r + R_)] =
                            acc[mt][nt][hr * 2 + cc] * rni * rn[b * N_ + gj];
                }
            }
        }
    }
}

// ---------------------------------------------------------------------------
// LayerNorm -> split-bf16 directly (+ optional rep inverse-norm)
// ---------------------------------------------------------------------------
__global__ void __launch_bounds__(128) ln_split(
    const float* __restrict__ in, const float* __restrict__ gam,
    const float* __restrict__ bet, __nv_bfloat16* __restrict__ ohi,
    __nv_bfloat16* __restrict__ olo, float* __restrict__ rnorm)
{
    const int row = blockIdx.x;
    const int t = threadIdx.x;
    const float4 v = ((const float4*)(in + (size_t)row * D_))[t];

    float s  = v.x + v.y + v.z + v.w;
    float ss = v.x*v.x + v.y*v.y + v.z*v.z + v.w*v.w;
    __shared__ float redA[4], redB[4], redC[4];
    #pragma unroll
    for (int o = 16; o > 0; o >>= 1) {
        s  += __shfl_xor_sync(0xffffffffu, s,  o);
        ss += __shfl_xor_sync(0xffffffffu, ss, o);
    }
    const int w = t >> 5;
    if ((t & 31) == 0) { redA[w] = s; redB[w] = ss; }
    __syncthreads();
    s  = redA[0] + redA[1] + redA[2] + redA[3];
    ss = redB[0] + redB[1] + redB[2] + redB[3];

    const float mean = s * (1.0f / D_);
    const float var  = ss * (1.0f / D_) - mean * mean;
    const float rstd = rsqrtf(var + 1e-5f);

    const float4 gv = ((const float4*)gam)[t];
    const float4 bv = ((const float4*)bet)[t];
    float4 xo;
    xo.x = (v.x - mean) * rstd * gv.x + bv.x;
    xo.y = (v.y - mean) * rstd * gv.y + bv.y;
    xo.z = (v.z - mean) * rstd * gv.z + bv.z;
    xo.w = (v.w - mean) * rstd * gv.w + bv.w;

    __nv_bfloat162 h0, h1, l0, l1;
    split_bf16(xo.x, h0.x, l0.x);
    split_bf16(xo.y, h0.y, l0.y);
    split_bf16(xo.z, h1.x, l1.x);
    split_bf16(xo.w, h1.y, l1.y);
    ((__nv_bfloat162*)(ohi + (size_t)row * D_))[2*t]   = h0;
    ((__nv_bfloat162*)(ohi + (size_t)row * D_))[2*t+1] = h1;
    ((__nv_bfloat162*)(olo + (size_t)row * D_))[2*t]   = l0;
    ((__nv_bfloat162*)(olo + (size_t)row * D_))[2*t+1] = l1;

    if (rnorm != nullptr) {
        float q = xo.x*xo.x + xo.y*xo.y + xo.z*xo.z + xo.w*xo.w;
        #pragma unroll
        for (int o = 16; o > 0; o >>= 1) q += __shfl_xor_sync(0xffffffffu, q, o);
        if ((t & 31) == 0) redC[w] = q;
        __syncthreads();
        if (t == 0) {
            float tot = redC[0] + redC[1] + redC[2] + redC[3];
            rnorm[row] = 1.0f / fmaxf(sqrtf(tot), 1e-12f);
        }
    }
}

// ---------------------------------------------------------------------------
// fused weight transpose + split: all four weights in ONE launch
// W [K,Nc] fp32 -> T [Nc,K] bf16 hi/lo
// ---------------------------------------------------------------------------
__global__ void __launch_bounds__(256) wtr_all(
    const float* __restrict__ w_qkv, const float* __restrict__ w_proj,
    const float* __restrict__ w_m1, const float* __restrict__ w_m2,
    __nv_bfloat16* __restrict__ Thi, __nv_bfloat16* __restrict__ Tlo)
{
    int bid = blockIdx.x;
    const float* W; int K, Nc, nx, off;
    if (bid < 768)       { W = w_qkv;  K = 512;  Nc = 1536; nx = 48; off = OFF_QKV; }
    else if (bid < 1024) { bid -= 768;  W = w_proj; K = 512;  Nc = 512;  nx = 16; off = OFF_PROJ; }
    else if (bid < 1536) { bid -= 1024; W = w_m1;   K = 512;  Nc = 1024; nx = 32; off = OFF_M1; }
    else                 { bid -= 1536; W = w_m2;   K = 1024; Nc = 512;  nx = 16; off = OFF_M2; }
    const int n0 = (bid % nx) * 32, k0 = (bid / nx) * 32;

    __shared__ float tile[32][33];
    const int tx = threadIdx.x & 31, ty = threadIdx.x >> 5;   // 32x8
    #pragma unroll
    for (int r = 0; r < 32; r += 8)
        tile[ty + r][tx] = W[(size_t)(k0 + ty + r) * Nc + n0 + tx];
    __syncthreads();
    #pragma unroll
    for (int r = 0; r < 32; r += 8) {
        const float v = tile[tx][ty + r];
        const __nv_bfloat16 h = __float2bfloat16(v);
        const size_t o = (size_t)off + (size_t)(n0 + ty + r) * K + k0 + tx;
        Thi[o] = h;
        Tlo[o] = __float2bfloat16(v - __bfloat162float(h));
    }
}

// ---------------------------------------------------------------------------
// banded attention: 2 threads per query, output written as split-bf16
// ---------------------------------------------------------------------------
__global__ void __launch_bounds__(256) attn_k(
    const float* __restrict__ qkv, const float* __restrict__ corrT,
    const float* __restrict__ rel_bias, const float* __restrict__ rep_scale,
    __nv_bfloat16* __restrict__ uhi, __nv_bfloat16* __restrict__ ulo)
{
    const int qt = blockIdx.x, h = blockIdx.y, b = blockIdx.z;
    const int q0 = qt * 128;
    const int t  = threadIdx.x;
    const int qi = t >> 1;
    const int hf = t & 1;
    const int i  = q0 + qi;
    const float rs = rep_scale[h];

    __shared__ float Ks[64][64];
    __shared__ float Vs[64][64];
    __shared__ float bias_s[BAND_];
    for (int r = t; r < BAND_; r += 256)
        bias_s[r] = rel_bias[(size_t)(r - R_ + N_ - 1) * H_ + h];

    float4 q4[8];
    const float4* qp = (const float4*)(qkv + (size_t)(b * N_ + i) * (3 * D_)
                                       + h * HD_ + hf * 32);
    #pragma unroll
    for (int c = 0; c < 8; c++) q4[c] = qp[c];

    float m = -1e29f, l = 0.f;
    float4 a4[8];
    #pragma unroll
    for (int c = 0; c < 8; c++) a4[c] = make_float4(0.f, 0.f, 0.f, 0.f);

    const int j0 = q0 - 64;
    const int w = t >> 5;
    const int iw0 = q0 + w * 16;
    const int jlo = max(0, iw0 - R_);
    const int jhi = min(N_ - 1, iw0 + 15 + R_);

    for (int cch = 0; cch < 4; cch++) {
        const int cbase = j0 + cch * 64;
        __syncthreads();
        for (int idx = t; idx < 64 * 16; idx += 256) {
            const int rrow = idx >> 4, c4 = idx & 15;
            const int j = cbase + rrow;
            float4 kv = make_float4(0.f, 0.f, 0.f, 0.f), vv = kv;
            if (j >= 0 && j < N_) {
                const float* base = qkv + (size_t)(b * N_ + j) * (3 * D_) + h * HD_;
                kv = *(const float4*)(base + D_     + c4 * 4);
                vv = *(const float4*)(base + 2 * D_ + c4 * 4);
            }
            ((float4*)&Ks[0][0])[idx] = kv;
            ((float4*)&Vs[0][0])[idx] = vv;
        }
        __syncthreads();

        const int lo = max(jlo, cbase), hi = min(jhi, cbase + 63);
        for (int jj = lo; jj <= hi; jj++) {
            const int kr = jj - cbase;
            const float4* kp = (const float4*)&Ks[kr][hf * 32];
            float s = 0.f;
            #pragma unroll
            for (int c = 0; c < 8; c++) {
                s = fmaf(q4[c].x, kp[c].x, s);
                s = fmaf(q4[c].y, kp[c].y, s);
                s = fmaf(q4[c].z, kp[c].z, s);
                s = fmaf(q4[c].w, kp[c].w, s);
            }
            s += __shfl_xor_sync(0xffffffffu, s, 1);
            const int r = i - jj;
            const int rc = min(max(r, -R_), R_);
            const float sv = s * 0.125f
                + corrT[(size_t)(b * N_ + jj) * BAND_ + rc + R_] * rs
                + bias_s[rc + R_];
            s = (r >= -R_ && r <= R_) ? sv : -1e30f;

            const float mn = fmaxf(m, s);
            if (mn > m) {
                const float sc = __expf(m - mn);
                l *= sc;
                #pragma unroll
                for (int c = 0; c < 8; c++) {
                    a4[c].x *= sc; a4[c].y *= sc; a4[c].z *= sc; a4[c].w *= sc;
                }
                m = mn;
            }
            const float p = __expf(s - m);
            l += p;
            const float4* vp = (const float4*)&Vs[kr][hf * 32];
            #pragma unroll
            for (int c = 0; c < 8; c++) {
                a4[c].x = fmaf(p, vp[c].x, a4[c].x);
                a4[c].y = fmaf(p, vp[c].y, a4[c].y);
                a4[c].z = fmaf(p, vp[c].z, a4[c].z);
                a4[c].w = fmaf(p, vp[c].w, a4[c].w);
            }
        }
    }

    const float inv = 1.0f / l;
    const size_t obase = (size_t)(b * N_ + i) * D_ + h * HD_ + hf * 32;
    #pragma unroll
    for (int c = 0; c < 8; c++) {
        __nv_bfloat162 h0, h1, l0, l1;
        split_bf16(a4[c].x * inv, h0.x, l0.x);
        split_bf16(a4[c].y * inv, h0.y, l0.y);
        split_bf16(a4[c].z * inv, h1.x, l1.x);
        split_bf16(a4[c].w * inv, h1.y, l1.y);
        ((__nv_bfloat162*)(uhi + obase))[2*c]   = h0;
        ((__nv_bfloat162*)(uhi + obase))[2*c+1] = h1;
        ((__nv_bfloat162*)(ulo + obase))[2*c]   = l0;
        ((__nv_bfloat162*)(ulo + obase))[2*c+1] = l1;
    }
}

// ---------------------------------------------------------------------------
// launcher
// ---------------------------------------------------------------------------
extern "C" void kernel_launch(void* const* d_in, const int* in_sizes, int n_in,
                              void* d_out, int out_size)
{
    const float* nodes  = (const float*)d_in[0];
    const float* ln1_g  = (const float*)d_in[1];
    const float* ln1_b  = (const float*)d_in[2];
    const float* qkv_w  = (const float*)d_in[3];
    const float* qkv_b  = (const float*)d_in[4];
    const float* proj_w = (const float*)d_in[5];
    const float* proj_b = (const float*)d_in[6];
    const float* rep_s  = (const float*)d_in[7];
    const float* rel_b  = (const float*)d_in[8];
    const float* ln2_g  = (const float*)d_in[9];
    const float* ln2_b  = (const float*)d_in[10];
    const float* mlp_w1 = (const float*)d_in[11];
    const float* mlp_b1 = (const float*)d_in[12];
    const float* mlp_w2 = (const float*)d_in[13];
    const float* mlp_b2 = (const float*)d_in[14];
    float* out = (float*)d_out;

    float *rn, *qkv, *corr, *n2;
    __nv_bfloat16 *ahi, *alo, *whi, *wlo;
    cudaGetSymbolAddress((void**)&rn,   g_rn);
    cudaGetSymbolAddress((void**)&qkv,  g_qkv);
    cudaGetSymbolAddress((void**)&corr, g_corr);
    cudaGetSymbolAddress((void**)&n2,   g_n2);
    cudaGetSymbolAddress((void**)&ahi,  g_act_hi);
    cudaGetSymbolAddress((void**)&alo,  g_act_lo);
    cudaGetSymbolAddress((void**)&whi,  g_wt_hi);
    cudaGetSymbolAddress((void**)&wlo,  g_wt_lo);

    // hb region: second segment of the activation planes (disjoint from first)
    __nv_bfloat16* hbhi = ahi + (size_t)BNROWS * D_;
    __nv_bfloat16* hblo = alo + (size_t)BNROWS * D_;

    cudaFuncSetAttribute(mma_gemm<0>, cudaFuncAttributeMaxDynamicSharedMemorySize, SMEM_GEMM);
    cudaFuncSetAttribute(mma_gemm<1>, cudaFuncAttributeMaxDynamicSharedMemorySize, SMEM_GEMM);
    cudaFuncSetAttribute(mma_gemm<2>, cudaFuncAttributeMaxDynamicSharedMemorySize, SMEM_GEMM);
    cudaFuncSetAttribute(mma_corr,    cudaFuncAttributeMaxDynamicSharedMemorySize, SMEM_GEMM);

    // 0) all weight transposes + split in one launch
    wtr_all<<<2048, 256>>>(qkv_w, proj_w, mlp_w1, mlp_w2, whi, wlo);

    // 1) LN1 -> split bf16 + rep inverse-norm
    ln_split<<<BNROWS, 128>>>(nodes, ln1_g, ln1_b, ahi, alo, rn);
    // 2) QKV projection (fp32 out for attention)
    mma_gemm<0><<<dim3(12, 32), 256, SMEM_GEMM>>>(
        ahi, alo, whi + OFF_QKV, wlo + OFF_QKV, qkv_b, nullptr, qkv,
        nullptr, nullptr, BNROWS, 3 * D_, D_);
    // 3) banded correlation (HMMA on X@X^T diagonal tiles)
    mma_corr<<<dim3(48, B_), 256, SMEM_GEMM>>>(ahi, alo, rn, corr);
    // 4) banded attention -> split bf16 upd (overwrites first act segment)
    attn_k<<<dim3(N_ / 128, H_, B_), 256>>>(qkv, corr, rel_b, rep_s, ahi, alo);
    // 5) output projection + residual -> n2 fp32
    mma_gemm<1><<<dim3(4, 32), 256, SMEM_GEMM>>>(
        ahi, alo, whi + OFF_PROJ, wlo + OFF_PROJ, proj_b, nodes, n2,
        nullptr, nullptr, BNROWS, D_, D_);
    // 6) LN2 -> split bf16
    ln_split<<<BNROWS, 128>>>(n2, ln2_g, ln2_b, ahi, alo, nullptr);
    // 7) MLP up + gelu -> split bf16 hb (second act segment, in-bounds now)
    mma_gemm<2><<<dim3(8, 32), 256, SMEM_GEMM>>>(
        ahi, alo, whi + OFF_M1, wlo + OFF_M1, mlp_b1, nullptr, nullptr,
        hbhi, hblo, BNROWS, 2 * D_, D_);
    // 8) MLP down + residual -> out
    mma_gemm<1><<<dim3(4, 32), 256, SMEM_GEMM>>>(
        hbhi, hblo, whi + OFF_M2, wlo + OFF_M2, mlp_b2, n2, out,
        nullptr, nullptr, BNROWS, D_, 2 * D_);
}

// round 14
// speedup vs baseline: 1.1299x; 1.0680x over previous
#include <cuda_runtime.h>
#include <cuda_bf16.h>
#include <math.h>
#include <stdint.h>

#define B_    2
#define N_    2048
#define D_    512
#define H_    8
#define HD_   64
#define R_    64
#define BAND_ 129
#define BNROWS (B_*N_)     // 4096

// ---------------------------------------------------------------------------
// scratch (static device globals: no allocation)
// ---------------------------------------------------------------------------
__device__ float g_rn  [BNROWS];
__device__ float g_qkv [BNROWS * 3 * D_];
__device__ float g_corr[BNROWS * BAND_];
__device__ float g_n2  [BNROWS * D_];

// activation split-bf16 planes:
//   [0 .. BNROWS*D_)           : 512-wide activation (x / upd / y)
//   [BNROWS*D_ .. BNROWS*3*D_) : 1024-wide gelu output hb
__device__ __nv_bfloat16 g_act_hi[BNROWS * 3 * D_];
__device__ __nv_bfloat16 g_act_lo[BNROWS * 3 * D_];

#define OFF_QKV  0
#define OFF_PROJ (1536*512)
#define OFF_M1   (OFF_PROJ + 512*512)
#define OFF_M2   (OFF_M1 + 1024*512)
#define WT_TOTAL (OFF_M2 + 512*1024)
__device__ __nv_bfloat16 g_wt_hi[WT_TOTAL];           // transposed weights [Nc,K]
__device__ __nv_bfloat16 g_wt_lo[WT_TOTAL];

// ---------------------------------------------------------------------------
// baseline-PTX building blocks (NO sm_103a-only instructions)
// ---------------------------------------------------------------------------
__device__ __forceinline__ uint32_t smem_to_u32(const void* p) {
    uint32_t a;
    asm("{ .reg .u64 t; cvta.to.shared.u64 t, %1; cvt.u32.u64 %0, t; }"
        : "=r"(a) : "l"(p));
    return a;
}

__device__ __forceinline__ void cp16(uint32_t dst, const void* src) {
    asm volatile("cp.async.cg.shared.global [%0], [%1], 16;\n"
        :: "r"(dst), "l"(__cvta_generic_to_global(src)) : "memory");
}
// zero-fill variant: src-size register (0 -> all zeros)
__device__ __forceinline__ void cp16z(uint32_t dst, const void* src, uint32_t sz) {
    asm volatile("cp.async.cg.shared.global [%0], [%1], 16, %2;\n"
        :: "r"(dst), "l"(__cvta_generic_to_global(src)), "r"(sz) : "memory");
}
__device__ __forceinline__ void cp_commit() {
    asm volatile("cp.async.commit_group;\n" ::: "memory");
}
template<int n> __device__ __forceinline__ void cp_wait() {
    asm volatile("cp.async.wait_group %0;\n" :: "n"(n) : "memory");
}

__device__ __forceinline__ void ldsm_x4(uint32_t (&r)[4], uint32_t addr) {
    asm volatile("ldmatrix.sync.aligned.m8n8.x4.shared.b16 {%0,%1,%2,%3}, [%4];"
        : "=r"(r[0]), "=r"(r[1]), "=r"(r[2]), "=r"(r[3]) : "r"(addr));
}

__device__ __forceinline__ void mma16816(float (&d)[4], const uint32_t (&a)[4],
                                         uint32_t b0, uint32_t b1) {
    asm volatile(
        "mma.sync.aligned.m16n8k16.row.col.f32.bf16.bf16.f32 "
        "{%0,%1,%2,%3}, {%4,%5,%6,%7}, {%8,%9}, {%0,%1,%2,%3};"
        : "+f"(d[0]), "+f"(d[1]), "+f"(d[2]), "+f"(d[3])
        : "r"(a[0]), "r"(a[1]), "r"(a[2]), "r"(a[3]), "r"(b0), "r"(b1));
}

__device__ __forceinline__ void split_bf16(float v, __nv_bfloat16& h, __nv_bfloat16& l) {
    h = __float2bfloat16(v);
    l = __float2bfloat16(v - __bfloat162float(h));
}

// ---------------------------------------------------------------------------
// GEMM core: C[128,BN] tile, BK=32, 8 warps (4m x 2n), warp tile 32m x (BN/2)n.
// 3-pass split-bf16: hi*hi + hi*lo + lo*hi, fp32 accumulate.
// smem rows padded to 80B (conflict-free ldmatrix).
// Stage layout: Ahi @0 (10240B), Alo @A_SZ, Bhi @2*A_SZ, Blo @2*A_SZ+BN*80.
// ---------------------------------------------------------------------------
#define LDSB   80
#define A_SZ   (128 * LDSB)     // 10240

template<int BN, bool CLAMPB>
__device__ __forceinline__ void stage_load(
    uint32_t sbase,
    const __nv_bfloat16* __restrict__ Ahi, const __nv_bfloat16* __restrict__ Alo,
    const __nv_bfloat16* __restrict__ Bhi, const __nv_bfloat16* __restrict__ Blo,
    int aRow0, int bRow0, int bLo, int bHi, int K, int kc, int tid)
{
    constexpr int BSZ = BN * LDSB;
    #pragma unroll
    for (int g = 0; g < 2; g++) {                 // A: 512 granules
        const int idx = g * 256 + tid;
        const int row = idx >> 2, c4 = idx & 3;
        const uint32_t soff = (uint32_t)row * LDSB + c4 * 16;
        const size_t ao = (size_t)(aRow0 + row) * K + kc + c4 * 8;
        cp16(sbase + soff, Ahi + ao);
        cp16(sbase + A_SZ + soff, Alo + ao);
    }
    #pragma unroll
    for (int g = 0; g < BN / 64; g++) {           // B: BN*4 granules
        const int idx = g * 256 + tid;
        const int row = idx >> 2, c4 = idx & 3;
        const uint32_t soff = (uint32_t)row * LDSB + c4 * 16;
        const int brow = bRow0 + row;
        if (CLAMPB) {
            const uint32_t sz = (brow >= bLo && brow < bHi) ? 16u : 0u;
            const int br = brow < bLo ? bLo : (brow >= bHi ? bHi - 1 : brow);
            const size_t bo = (size_t)br * K + kc + c4 * 8;
            cp16z(sbase + 2 * A_SZ + soff, Bhi + bo, sz);
            cp16z(sbase + 2 * A_SZ + BSZ + soff, Blo + bo, sz);
        } else {
            const size_t bo = (size_t)brow * K + kc + c4 * 8;
            cp16(sbase + 2 * A_SZ + soff, Bhi + bo);
            cp16(sbase + 2 * A_SZ + BSZ + soff, Blo + bo);
        }
    }
}

template<int NP>
__device__ __forceinline__ void stage_compute(
    uint32_t sbase, float (&acc)[2][2*NP][4], int wm, int wn, int lane)
{
    constexpr int BSZ = NP * 32 * LDSB;           // BN*LDSB
    const int rA = lane & 15, gA = lane >> 4;
    const int grp = lane >> 3, rB = lane & 7;
    const int nof = (grp >> 1) * 8 + rB, kof = (grp & 1) * 8;
    const uint32_t bbase = sbase + 2 * A_SZ;

    #pragma unroll
    for (int ks = 0; ks < 2; ks++) {
        uint32_t ah[2][4], al[2][4];
        #pragma unroll
        for (int mt = 0; mt < 2; mt++) {
            const uint32_t aaddr = sbase
                + (uint32_t)(wm * 32 + mt * 16 + rA) * LDSB + (ks * 16 + gA * 8) * 2;
            ldsm_x4(ah[mt], aaddr);
            ldsm_x4(al[mt], aaddr + A_SZ);
        }
        #pragma unroll
        for (int np = 0; np < NP; np++) {
            uint32_t bh[4], bl[4];
            const uint32_t baddr = bbase
                + (uint32_t)(wn * (NP * 16) + np * 16 + nof) * LDSB
                + (ks * 16 + kof) * 2;
            ldsm_x4(bh, baddr);
            ldsm_x4(bl, baddr + BSZ);
            #pragma unroll
            for (int mt = 0; mt < 2; mt++) {
                #pragma unroll
                for (int hn = 0; hn < 2; hn++) {
                    float (&d)[4] = acc[mt][np * 2 + hn];
                    mma16816(d, ah[mt], bh[hn * 2], bh[hn * 2 + 1]);
                    mma16816(d, ah[mt], bl[hn * 2], bl[hn * 2 + 1]);
                    mma16816(d, al[mt], bh[hn * 2], bh[hn * 2 + 1]);
                }
            }
        }
    }
}

template<int BN, bool CLAMPB>
__device__ __forceinline__ void run_gemm(
    char* smem_c, float (&acc)[2][BN/16][4],
    const __nv_bfloat16* Ahi, const __nv_bfloat16* Alo,
    const __nv_bfloat16* Bhi, const __nv_bfloat16* Blo,
    int aRow0, int bRow0, int bLo, int bHi, int K)
{
    constexpr int NP = BN / 32;
    constexpr int STAGE = 2 * A_SZ + 2 * BN * LDSB;
    const uint32_t sb = smem_to_u32(smem_c);
    const int tid = threadIdx.x;
    const int wid = tid >> 5, lane = tid & 31;
    const int wm = wid & 3, wn = wid >> 2;

    #pragma unroll
    for (int i = 0; i < 2; i++)
        #pragma unroll
        for (int j = 0; j < BN/16; j++)
            #pragma unroll
            for (int k = 0; k < 4; k++) acc[i][j][k] = 0.f;

    const int nit = K / 32;
    stage_load<BN,CLAMPB>(sb, Ahi, Alo, Bhi, Blo, aRow0, bRow0, bLo, bHi, K, 0, tid);
    cp_commit();
    for (int it = 0; it < nit; it++) {
        if (it + 1 < nit) {
            stage_load<BN,CLAMPB>(sb + ((it + 1) & 1) * STAGE, Ahi, Alo, Bhi, Blo,
                                  aRow0, bRow0, bLo, bHi, K, (it + 1) * 32, tid);
            cp_commit();
            cp_wait<1>();
        } else {
            cp_wait<0>();
        }
        __syncthreads();
        stage_compute<NP>(sb + (it & 1) * STAGE, acc, wm, wn, lane);
        __syncthreads();
    }
}

// ---------------------------------------------------------------------------
// standalone GEMM kernel. EPI: 1 = +bias+residual -> fp32 C
//                              2 = +bias+exact gelu -> split-bf16 (Chi/Clo)
// ---------------------------------------------------------------------------
template<int EPI, int BN>
__global__ void __launch_bounds__(256, 2) mma_gemm(
    const __nv_bfloat16* __restrict__ Ahi, const __nv_bfloat16* __restrict__ Alo,
    const __nv_bfloat16* __restrict__ Bhi, const __nv_bfloat16* __restrict__ Blo,
    const float* __restrict__ bias, const float* __restrict__ res,
    float* __restrict__ C, __nv_bfloat16* __restrict__ Chi,
    __nv_bfloat16* __restrict__ Clo, int M, int Nc, int K)
{
    extern __shared__ char smem[];
    constexpr int NP = BN / 32;
    float acc[2][BN/16][4];
    const int m0 = blockIdx.y * 128, n0 = blockIdx.x * BN;
    run_gemm<BN,false>(smem, acc, Ahi, Alo, Bhi, Blo, m0, n0, 0, 0x7fffffff, K);

    const int wid = threadIdx.x >> 5, lane = threadIdx.x & 31;
    const int wm = wid & 3, wn = wid >> 2;
    const int g = lane >> 2, tg = lane & 3;

    #pragma unroll
    for (int nt = 0; nt < BN/16; nt++) {
        const int col = n0 + wn * (NP * 16) + nt * 8 + 2 * tg;
        const float b0 = bias[col], b1 = bias[col + 1];
        #pragma unroll
        for (int mt = 0; mt < 2; mt++) {
            #pragma unroll
            for (int hr = 0; hr < 2; hr++) {
                const int row = m0 + wm * 32 + mt * 16 + g + hr * 8;
                float vx = acc[mt][nt][hr * 2 + 0] + b0;
                float vy = acc[mt][nt][hr * 2 + 1] + b1;
                if (EPI == 1) {
                    const float2 r2 = *(const float2*)(res + (size_t)row * Nc + col);
                    vx += r2.x; vy += r2.y;
                    float2 o; o.x = vx; o.y = vy;
                    *(float2*)(C + (size_t)row * Nc + col) = o;
                } else {
                    vx = 0.5f * vx * (1.0f + erff(vx * 0.70710678118654752f));
                    vy = 0.5f * vy * (1.0f + erff(vy * 0.70710678118654752f));
                    __nv_bfloat162 h2, l2;
                    split_bf16(vx, h2.x, l2.x);
                    split_bf16(vy, h2.y, l2.y);
                    *(__nv_bfloat162*)(Chi + (size_t)row * Nc + col) = h2;
                    *(__nv_bfloat162*)(Clo + (size_t)row * Nc + col) = l2;
                }
            }
        }
    }
}

// ---------------------------------------------------------------------------
// fused QKV projection + banded correlation, one launch.
// blocks [0,384): QKV tiles (12 n-tiles x 32 m-tiles), BN=128, K=512
// blocks [384,448): corr tiles, 2 per 128-row block at n0 = m0-64 + side*128
// ---------------------------------------------------------------------------
__global__ void __launch_bounds__(256, 2) mma_qkv_corr(
    const __nv_bfloat16* __restrict__ Xhi, const __nv_bfloat16* __restrict__ Xlo,
    const __nv_bfloat16* __restrict__ Whi, const __nv_bfloat16* __restrict__ Wlo,
    const float* __restrict__ bias, float* __restrict__ Cqkv,
    const float* __restrict__ rn, float* __restrict__ corrT)
{
    extern __shared__ char smem[];
    const int wid = threadIdx.x >> 5, lane = threadIdx.x & 31;
    const int wm = wid & 3, wn = wid >> 2;
    const int g = lane >> 2, tg = lane & 3;

    if (blockIdx.x < 384) {
        float acc[2][8][4];
        const int n0 = (blockIdx.x % 12) * 128, m0 = (blockIdx.x / 12) * 128;
        run_gemm<128,false>(smem, acc, Xhi, Xlo, Whi, Wlo, m0, n0, 0, 0x7fffffff, D_);

        #pragma unroll
        for (int nt = 0; nt < 8; nt++) {
            const int col = n0 + wn * 64 + nt * 8 + 2 * tg;
            const float b0 = bias[col], b1 = bias[col + 1];
            #pragma unroll
            for (int mt = 0; mt < 2; mt++) {
                #pragma unroll
                for (int hr = 0; hr < 2; hr++) {
                    const int row = m0 + wm * 32 + mt * 16 + g + hr * 8;
                    float2 o;
                    o.x = acc[mt][nt][hr * 2 + 0] + b0;
                    o.y = acc[mt][nt][hr * 2 + 1] + b1;
                    *(float2*)(Cqkv + (size_t)row * (3 * D_) + col) = o;
                }
            }
        }
    } else {
        const int cid = blockIdx.x - 384;        // 0..63
        const int b = cid >> 5;
        const int t2 = cid & 31;
        const int bi = t2 >> 1, side = t2 & 1;
        const int m0 = bi * 128;
        const int n0 = m0 - 64 + side * 128;
        float acc[2][8][4];
        run_gemm<128,true>(smem, acc, Xhi, Xlo, Xhi, Xlo,
                           b * N_ + m0, b * N_ + n0, b * N_, b * N_ + N_, D_);

        #pragma unroll
        for (int mt = 0; mt < 2; mt++) {
            #pragma unroll
            for (int hr = 0; hr < 2; hr++) {
                const int gi = m0 + wm * 32 + mt * 16 + g + hr * 8;
                const float rni = rn[b * N_ + gi];
                #pragma unroll
                for (int nt = 0; nt < 8; nt++) {
                    #pragma unroll
                    for (int cc = 0; cc < 2; cc++) {
                        const int gj = n0 + wn * 64 + nt * 8 + 2 * tg + cc;
                        const int r = gi - gj;
                        if (r >= -R_ && r <= R_ && gj >= 0 && gj < N_)
                            corrT[(size_t)(b * N_ + gj) * BAND_ + (r + R_)] =
                                acc[mt][nt][hr * 2 + cc] * rni * rn[b * N_ + gj];
                    }
                }
            }
        }
    }
}

// ---------------------------------------------------------------------------
// LayerNorm -> split-bf16 directly (+ optional rep inverse-norm)
// ---------------------------------------------------------------------------
__global__ void __launch_bounds__(128) ln_split(
    const float* __restrict__ in, const float* __restrict__ gam,
    const float* __restrict__ bet, __nv_bfloat16* __restrict__ ohi,
    __nv_bfloat16* __restrict__ olo, float* __restrict__ rnorm)
{
    const int row = blockIdx.x;
    const int t = threadIdx.x;
    const float4 v = ((const float4*)(in + (size_t)row * D_))[t];

    float s  = v.x + v.y + v.z + v.w;
    float ss = v.x*v.x + v.y*v.y + v.z*v.z + v.w*v.w;
    __shared__ float redA[4], redB[4], redC[4];
    #pragma unroll
    for (int o = 16; o > 0; o >>= 1) {
        s  += __shfl_xor_sync(0xffffffffu, s,  o);
        ss += __shfl_xor_sync(0xffffffffu, ss, o);
    }
    const int w = t >> 5;
    if ((t & 31) == 0) { redA[w] = s; redB[w] = ss; }
    __syncthreads();
    s  = redA[0] + redA[1] + redA[2] + redA[3];
    ss = redB[0] + redB[1] + redB[2] + redB[3];

    const float mean = s * (1.0f / D_);
    const float var  = ss * (1.0f / D_) - mean * mean;
    const float rstd = rsqrtf(var + 1e-5f);

    const float4 gv = ((const float4*)gam)[t];
    const float4 bv = ((const float4*)bet)[t];
    float4 xo;
    xo.x = (v.x - mean) * rstd * gv.x + bv.x;
    xo.y = (v.y - mean) * rstd * gv.y + bv.y;
    xo.z = (v.z - mean) * rstd * gv.z + bv.z;
    xo.w = (v.w - mean) * rstd * gv.w + bv.w;

    __nv_bfloat162 h0, h1, l0, l1;
    split_bf16(xo.x, h0.x, l0.x);
    split_bf16(xo.y, h0.y, l0.y);
    split_bf16(xo.z, h1.x, l1.x);
    split_bf16(xo.w, h1.y, l1.y);
    ((__nv_bfloat162*)(ohi + (size_t)row * D_))[2*t]   = h0;
    ((__nv_bfloat162*)(ohi + (size_t)row * D_))[2*t+1] = h1;
    ((__nv_bfloat162*)(olo + (size_t)row * D_))[2*t]   = l0;
    ((__nv_bfloat162*)(olo + (size_t)row * D_))[2*t+1] = l1;

    if (rnorm != nullptr) {
        float q = xo.x*xo.x + xo.y*xo.y + xo.z*xo.z + xo.w*xo.w;
        #pragma unroll
        for (int o = 16; o > 0; o >>= 1) q += __shfl_xor_sync(0xffffffffu, q, o);
        if ((t & 31) == 0) redC[w] = q;
        __syncthreads();
        if (t == 0) {
            float tot = redC[0] + redC[1] + redC[2] + redC[3];
            rnorm[row] = 1.0f / fmaxf(sqrtf(tot), 1e-12f);
        }
    }
}

// ---------------------------------------------------------------------------
// fused weight transpose + split (one launch)
// ---------------------------------------------------------------------------
__global__ void __launch_bounds__(256) wtr_all(
    const float* __restrict__ w_qkv, const float* __restrict__ w_proj,
    const float* __restrict__ w_m1, const float* __restrict__ w_m2,
    __nv_bfloat16* __restrict__ Thi, __nv_bfloat16* __restrict__ Tlo)
{
    int bid = blockIdx.x;
    const float* W; int K, Nc, nx, off;
    if (bid < 768)       { W = w_qkv;  K = 512;  Nc = 1536; nx = 48; off = OFF_QKV; }
    else if (bid < 1024) { bid -= 768;  W = w_proj; K = 512;  Nc = 512;  nx = 16; off = OFF_PROJ; }
    else if (bid < 1536) { bid -= 1024; W = w_m1;   K = 512;  Nc = 1024; nx = 32; off = OFF_M1; }
    else                 { bid -= 1536; W = w_m2;   K = 1024; Nc = 512;  nx = 16; off = OFF_M2; }
    const int n0 = (bid % nx) * 32, k0 = (bid / nx) * 32;

    __shared__ float tile[32][33];
    const int tx = threadIdx.x & 31, ty = threadIdx.x >> 5;
    #pragma unroll
    for (int r = 0; r < 32; r += 8)
        tile[ty + r][tx] = W[(size_t)(k0 + ty + r) * Nc + n0 + tx];
    __syncthreads();
    #pragma unroll
    for (int r = 0; r < 32; r += 8) {
        const float v = tile[tx][ty + r];
        const __nv_bfloat16 h = __float2bfloat16(v);
        const size_t o = (size_t)off + (size_t)(n0 + ty + r) * K + k0 + tx;
        Thi[o] = h;
        Tlo[o] = __float2bfloat16(v - __bfloat162float(h));
    }
}

// ---------------------------------------------------------------------------
// banded attention: 2 threads per query, output written as split-bf16
// ---------------------------------------------------------------------------
__global__ void __launch_bounds__(256) attn_k(
    const float* __restrict__ qkv, const float* __restrict__ corrT,
    const float* __restrict__ rel_bias, const float* __restrict__ rep_scale,
    __nv_bfloat16* __restrict__ uhi, __nv_bfloat16* __restrict__ ulo)
{
    const int qt = blockIdx.x, h = blockIdx.y, b = blockIdx.z;
    const int q0 = qt * 128;
    const int t  = threadIdx.x;
    const int qi = t >> 1;
    const int hf = t & 1;
    const int i  = q0 + qi;
    const float rs = rep_scale[h];

    __shared__ float Ks[64][64];
    __shared__ float Vs[64][64];
    __shared__ float bias_s[BAND_];
    for (int r = t; r < BAND_; r += 256)
        bias_s[r] = rel_bias[(size_t)(r - R_ + N_ - 1) * H_ + h];

    float4 q4[8];
    const float4* qp = (const float4*)(qkv + (size_t)(b * N_ + i) * (3 * D_)
                                       + h * HD_ + hf * 32);
    #pragma unroll
    for (int c = 0; c < 8; c++) q4[c] = qp[c];

    float m = -1e29f, l = 0.f;
    float4 a4[8];
    #pragma unroll
    for (int c = 0; c < 8; c++) a4[c] = make_float4(0.f, 0.f, 0.f, 0.f);

    const int j0 = q0 - 64;
    const int w = t >> 5;
    const int iw0 = q0 + w * 16;
    const int jlo = max(0, iw0 - R_);
    const int jhi = min(N_ - 1, iw0 + 15 + R_);

    for (int cch = 0; cch < 4; cch++) {
        const int cbase = j0 + cch * 64;
        __syncthreads();
        for (int idx = t; idx < 64 * 16; idx += 256) {
            const int rrow = idx >> 4, c4 = idx & 15;
            const int j = cbase + rrow;
            float4 kv = make_float4(0.f, 0.f, 0.f, 0.f), vv = kv;
            if (j >= 0 && j < N_) {
                const float* base = qkv + (size_t)(b * N_ + j) * (3 * D_) + h * HD_;
                kv = *(const float4*)(base + D_     + c4 * 4);
                vv = *(const float4*)(base + 2 * D_ + c4 * 4);
            }
            ((float4*)&Ks[0][0])[idx] = kv;
            ((float4*)&Vs[0][0])[idx] = vv;
        }
        __syncthreads();

        const int lo = max(jlo, cbase), hi = min(jhi, cbase + 63);
        for (int jj = lo; jj <= hi; jj++) {
            const int kr = jj - cbase;
            const float4* kp = (const float4*)&Ks[kr][hf * 32];
            float s = 0.f;
            #pragma unroll
            for (int c = 0; c < 8; c++) {
                s = fmaf(q4[c].x, kp[c].x, s);
                s = fmaf(q4[c].y, kp[c].y, s);
                s = fmaf(q4[c].z, kp[c].z, s);
                s = fmaf(q4[c].w, kp[c].w, s);
            }
            s += __shfl_xor_sync(0xffffffffu, s, 1);
            const int r = i - jj;
            const int rc = min(max(r, -R_), R_);
            const float sv = s * 0.125f
                + corrT[(size_t)(b * N_ + jj) * BAND_ + rc + R_] * rs
                + bias_s[rc + R_];
            s = (r >= -R_ && r <= R_) ? sv : -1e30f;

            const float mn = fmaxf(m, s);
            if (mn > m) {
                const float sc = __expf(m - mn);
                l *= sc;
                #pragma unroll
                for (int c = 0; c < 8; c++) {
                    a4[c].x *= sc; a4[c].y *= sc; a4[c].z *= sc; a4[c].w *= sc;
                }
                m = mn;
            }
            const float p = __expf(s - m);
            l += p;
            const float4* vp = (const float4*)&Vs[kr][hf * 32];
            #pragma unroll
            for (int c = 0; c < 8; c++) {
                a4[c].x = fmaf(p, vp[c].x, a4[c].x);
                a4[c].y = fmaf(p, vp[c].y, a4[c].y);
                a4[c].z = fmaf(p, vp[c].z, a4[c].z);
                a4[c].w = fmaf(p, vp[c].w, a4[c].w);
            }
        }
    }

    const float inv = 1.0f / l;
    const size_t obase = (size_t)(b * N_ + i) * D_ + h * HD_ + hf * 32;
    #pragma unroll
    for (int c = 0; c < 8; c++) {
        __nv_bfloat162 h0, h1, l0, l1;
        split_bf16(a4[c].x * inv, h0.x, l0.x);
        split_bf16(a4[c].y * inv, h0.y, l0.y);
        split_bf16(a4[c].z * inv, h1.x, l1.x);
        split_bf16(a4[c].w * inv, h1.y, l1.y);
        ((__nv_bfloat162*)(uhi + obase))[2*c]   = h0;
        ((__nv_bfloat162*)(uhi + obase))[2*c+1] = h1;
        ((__nv_bfloat162*)(ulo + obase))[2*c]   = l0;
        ((__nv_bfloat162*)(ulo + obase))[2*c+1] = l1;
    }
}

// ---------------------------------------------------------------------------
// launcher
// ---------------------------------------------------------------------------
#define SMEM128 (2 * (2 * A_SZ + 2 * 128 * LDSB))   // 81920
#define SMEM64  (2 * (2 * A_SZ + 2 *  64 * LDSB))   // 61440

extern "C" void kernel_launch(void* const* d_in, const int* in_sizes, int n_in,
                              void* d_out, int out_size)
{
    const float* nodes  = (const float*)d_in[0];
    const float* ln1_g  = (const float*)d_in[1];
    const float* ln1_b  = (const float*)d_in[2];
    const float* qkv_w  = (const float*)d_in[3];
    const float* qkv_b  = (const float*)d_in[4];
    const float* proj_w = (const float*)d_in[5];
    const float* proj_b = (const float*)d_in[6];
    const float* rep_s  = (const float*)d_in[7];
    const float* rel_b  = (const float*)d_in[8];
    const float* ln2_g  = (const float*)d_in[9];
    const float* ln2_b  = (const float*)d_in[10];
    const float* mlp_w1 = (const float*)d_in[11];
    const float* mlp_b1 = (const float*)d_in[12];
    const float* mlp_w2 = (const float*)d_in[13];
    const float* mlp_b2 = (const float*)d_in[14];
    float* out = (float*)d_out;

    float *rn, *qkv, *corr, *n2;
    __nv_bfloat16 *ahi, *alo, *whi, *wlo;
    cudaGetSymbolAddress((void**)&rn,   g_rn);
    cudaGetSymbolAddress((void**)&qkv,  g_qkv);
    cudaGetSymbolAddress((void**)&corr, g_corr);
    cudaGetSymbolAddress((void**)&n2,   g_n2);
    cudaGetSymbolAddress((void**)&ahi,  g_act_hi);
    cudaGetSymbolAddress((void**)&alo,  g_act_lo);
    cudaGetSymbolAddress((void**)&whi,  g_wt_hi);
    cudaGetSymbolAddress((void**)&wlo,  g_wt_lo);

    __nv_bfloat16* hbhi = ahi + (size_t)BNROWS * D_;
    __nv_bfloat16* hblo = alo + (size_t)BNROWS * D_;

    cudaFuncSetAttribute(mma_qkv_corr,
        cudaFuncAttributeMaxDynamicSharedMemorySize, SMEM128);
    cudaFuncSetAttribute(mma_gemm<1,64>,
        cudaFuncAttributeMaxDynamicSharedMemorySize, SMEM64);
    cudaFuncSetAttribute(mma_gemm<2,128>,
        cudaFuncAttributeMaxDynamicSharedMemorySize, SMEM128);

    // 0) weight transposes + split
    wtr_all<<<2048, 256>>>(qkv_w, proj_w, mlp_w1, mlp_w2, whi, wlo);
    // 1) LN1 -> split bf16 + rep inverse-norm
    ln_split<<<BNROWS, 128>>>(nodes, ln1_g, ln1_b, ahi, alo, rn);
    // 2) fused QKV projection + banded correlation (448 blocks)
    mma_qkv_corr<<<448, 256, SMEM128>>>(
        ahi, alo, whi + OFF_QKV, wlo + OFF_QKV, qkv_b, qkv, rn, corr);
    // 3) banded attention -> split bf16 upd
    attn_k<<<dim3(N_ / 128, H_, B_), 256>>>(qkv, corr, rel_b, rep_s, ahi, alo);
    // 4) output projection + residual -> n2 (BN=64, 256 blocks)
    mma_gemm<1,64><<<dim3(8, 32), 256, SMEM64>>>(
        ahi, alo, whi + OFF_PROJ, wlo + OFF_PROJ, proj_b, nodes, n2,
        nullptr, nullptr, BNROWS, D_, D_);
    // 5) LN2 -> split bf16
    ln_split<<<BNROWS, 128>>>(n2, ln2_g, ln2_b, ahi, alo, nullptr);
    // 6) MLP up + gelu -> split bf16 hb (BN=128, 256 blocks)
    mma_gemm<2,128><<<dim3(8, 32), 256, SMEM128>>>(
        ahi, alo, whi + OFF_M1, wlo + OFF_M1, mlp_b1, nullptr, nullptr,
        hbhi, hblo, BNROWS, 2 * D_, D_);
    // 7) MLP down + residual -> out (BN=64, 256 blocks, K=1024)
    mma_gemm<1,64><<<dim3(8, 32), 256, SMEM64>>>(
        hbhi, hblo, whi + OFF_M2, wlo + OFF_M2, mlp_b2, n2, out,
        nullptr, nullptr, BNROWS, D_, 2 * D_);
}

// round 15
// speedup vs baseline: 1.2204x; 1.0801x over previous
#include <cuda_runtime.h>
#include <cuda_bf16.h>
#include <math.h>
#include <stdint.h>

#define B_    2
#define N_    2048
#define D_    512
#define H_    8
#define HD_   64
#define R_    64
#define BAND_ 129
#define BNROWS (B_*N_)     // 4096

// ---------------------------------------------------------------------------
// scratch (static device globals: no allocation)
// ---------------------------------------------------------------------------
__device__ float g_rn  [BNROWS];
__device__ float g_qkv [BNROWS * 3 * D_];
__device__ float g_corr[BNROWS * BAND_];
__device__ float g_n2  [BNROWS * D_];

// activation split-bf16 planes:
//   [0 .. BNROWS*D_)           : 512-wide activation (x / upd / y)
//   [BNROWS*D_ .. BNROWS*3*D_) : 1024-wide gelu output hb
__device__ __nv_bfloat16 g_act_hi[BNROWS * 3 * D_];
__device__ __nv_bfloat16 g_act_lo[BNROWS * 3 * D_];

#define OFF_QKV  0
#define OFF_PROJ (1536*512)
#define OFF_M1   (OFF_PROJ + 512*512)
#define OFF_M2   (OFF_M1 + 1024*512)
#define WT_TOTAL (OFF_M2 + 512*1024)
__device__ __nv_bfloat16 g_wt_hi[WT_TOTAL];           // transposed weights [Nc,K]
__device__ __nv_bfloat16 g_wt_lo[WT_TOTAL];

// ---------------------------------------------------------------------------
// baseline-PTX building blocks (NO sm_103a-only instructions)
// ---------------------------------------------------------------------------
__device__ __forceinline__ uint32_t smem_to_u32(const void* p) {
    uint32_t a;
    asm("{ .reg .u64 t; cvta.to.shared.u64 t, %1; cvt.u32.u64 %0, t; }"
        : "=r"(a) : "l"(p));
    return a;
}

__device__ __forceinline__ void cp16(uint32_t dst, const void* src) {
    asm volatile("cp.async.cg.shared.global [%0], [%1], 16;\n"
        :: "r"(dst), "l"(__cvta_generic_to_global(src)) : "memory");
}
// zero-fill variant: src-size register (0 -> all zeros)
__device__ __forceinline__ void cp16z(uint32_t dst, const void* src, uint32_t sz) {
    asm volatile("cp.async.cg.shared.global [%0], [%1], 16, %2;\n"
        :: "r"(dst), "l"(__cvta_generic_to_global(src)), "r"(sz) : "memory");
}
__device__ __forceinline__ void cp_commit() {
    asm volatile("cp.async.commit_group;\n" ::: "memory");
}
template<int n> __device__ __forceinline__ void cp_wait() {
    asm volatile("cp.async.wait_group %0;\n" :: "n"(n) : "memory");
}

__device__ __forceinline__ void ldsm_x4(uint32_t (&r)[4], uint32_t addr) {
    asm volatile("ldmatrix.sync.aligned.m8n8.x4.shared.b16 {%0,%1,%2,%3}, [%4];"
        : "=r"(r[0]), "=r"(r[1]), "=r"(r[2]), "=r"(r[3]) : "r"(addr));
}

__device__ __forceinline__ void mma16816(float (&d)[4], const uint32_t (&a)[4],
                                         uint32_t b0, uint32_t b1) {
    asm volatile(
        "mma.sync.aligned.m16n8k16.row.col.f32.bf16.bf16.f32 "
        "{%0,%1,%2,%3}, {%4,%5,%6,%7}, {%8,%9}, {%0,%1,%2,%3};"
        : "+f"(d[0]), "+f"(d[1]), "+f"(d[2]), "+f"(d[3])
        : "r"(a[0]), "r"(a[1]), "r"(a[2]), "r"(a[3]), "r"(b0), "r"(b1));
}

__device__ __forceinline__ void split_bf16(float v, __nv_bfloat16& h, __nv_bfloat16& l) {
    h = __float2bfloat16(v);
    l = __float2bfloat16(v - __bfloat162float(h));
}

// ---------------------------------------------------------------------------
// GEMM core: C[128,BN] tile, BK=32, 8 warps (4m x 2n), warp tile 32m x (BN/2)n.
// 3-pass split-bf16: hi*hi + hi*lo + lo*hi, fp32 accumulate.
// smem rows padded to 80B (conflict-free ldmatrix).
// ---------------------------------------------------------------------------
#define LDSB   80
#define A_SZ   (128 * LDSB)     // 10240

template<int BN, bool CLAMPB>
__device__ __forceinline__ void stage_load(
    uint32_t sbase,
    const __nv_bfloat16* __restrict__ Ahi, const __nv_bfloat16* __restrict__ Alo,
    const __nv_bfloat16* __restrict__ Bhi, const __nv_bfloat16* __restrict__ Blo,
    int aRow0, int bRow0, int bLo, int bHi, int K, int kc, int tid)
{
    constexpr int BSZ = BN * LDSB;
    #pragma unroll
    for (int g = 0; g < 2; g++) {                 // A: 512 granules
        const int idx = g * 256 + tid;
        const int row = idx >> 2, c4 = idx & 3;
        const uint32_t soff = (uint32_t)row * LDSB + c4 * 16;
        const size_t ao = (size_t)(aRow0 + row) * K + kc + c4 * 8;
        cp16(sbase + soff, Ahi + ao);
        cp16(sbase + A_SZ + soff, Alo + ao);
    }
    #pragma unroll
    for (int g = 0; g < BN / 64; g++) {           // B: BN*4 granules
        const int idx = g * 256 + tid;
        const int row = idx >> 2, c4 = idx & 3;
        const uint32_t soff = (uint32_t)row * LDSB + c4 * 16;
        const int brow = bRow0 + row;
        if (CLAMPB) {
            const uint32_t sz = (brow >= bLo && brow < bHi) ? 16u : 0u;
            const int br = brow < bLo ? bLo : (brow >= bHi ? bHi - 1 : brow);
            const size_t bo = (size_t)br * K + kc + c4 * 8;
            cp16z(sbase + 2 * A_SZ + soff, Bhi + bo, sz);
            cp16z(sbase + 2 * A_SZ + BSZ + soff, Blo + bo, sz);
        } else {
            const size_t bo = (size_t)brow * K + kc + c4 * 8;
            cp16(sbase + 2 * A_SZ + soff, Bhi + bo);
            cp16(sbase + 2 * A_SZ + BSZ + soff, Blo + bo);
        }
    }
}

template<int NP>
__device__ __forceinline__ void stage_compute(
    uint32_t sbase, float (&acc)[2][2*NP][4], int wm, int wn, int lane)
{
    constexpr int BSZ = NP * 32 * LDSB;           // BN*LDSB
    const int rA = lane & 15, gA = lane >> 4;
    const int grp = lane >> 3, rB = lane & 7;
    const int nof = (grp >> 1) * 8 + rB, kof = (grp & 1) * 8;
    const uint32_t bbase = sbase + 2 * A_SZ;

    #pragma unroll
    for (int ks = 0; ks < 2; ks++) {
        uint32_t ah[2][4], al[2][4];
        #pragma unroll
        for (int mt = 0; mt < 2; mt++) {
            const uint32_t aaddr = sbase
                + (uint32_t)(wm * 32 + mt * 16 + rA) * LDSB + (ks * 16 + gA * 8) * 2;
            ldsm_x4(ah[mt], aaddr);
            ldsm_x4(al[mt], aaddr + A_SZ);
        }
        #pragma unroll
        for (int np = 0; np < NP; np++) {
            uint32_t bh[4], bl[4];
            const uint32_t baddr = bbase
                + (uint32_t)(wn * (NP * 16) + np * 16 + nof) * LDSB
                + (ks * 16 + kof) * 2;
            ldsm_x4(bh, baddr);
            ldsm_x4(bl, baddr + BSZ);
            #pragma unroll
            for (int mt = 0; mt < 2; mt++) {
                #pragma unroll
                for (int hn = 0; hn < 2; hn++) {
                    float (&d)[4] = acc[mt][np * 2 + hn];
                    mma16816(d, ah[mt], bh[hn * 2], bh[hn * 2 + 1]);
                    mma16816(d, ah[mt], bl[hn * 2], bl[hn * 2 + 1]);
                    mma16816(d, al[mt], bh[hn * 2], bh[hn * 2 + 1]);
                }
            }
        }
    }
}

template<int BN, bool CLAMPB>
__device__ __forceinline__ void run_gemm(
    char* smem_c, float (&acc)[2][BN/16][4],
    const __nv_bfloat16* Ahi, const __nv_bfloat16* Alo,
    const __nv_bfloat16* Bhi, const __nv_bfloat16* Blo,
    int aRow0, int bRow0, int bLo, int bHi, int K)
{
    constexpr int NP = BN / 32;
    constexpr int STAGE = 2 * A_SZ + 2 * BN * LDSB;
    const uint32_t sb = smem_to_u32(smem_c);
    const int tid = threadIdx.x;
    const int wid = tid >> 5, lane = tid & 31;
    const int wm = wid & 3, wn = wid >> 2;

    #pragma unroll
    for (int i = 0; i < 2; i++)
        #pragma unroll
        for (int j = 0; j < BN/16; j++)
            #pragma unroll
            for (int k = 0; k < 4; k++) acc[i][j][k] = 0.f;

    const int nit = K / 32;
    stage_load<BN,CLAMPB>(sb, Ahi, Alo, Bhi, Blo, aRow0, bRow0, bLo, bHi, K, 0, tid);
    cp_commit();
    for (int it = 0; it < nit; it++) {
        if (it + 1 < nit) {
            stage_load<BN,CLAMPB>(sb + ((it + 1) & 1) * STAGE, Ahi, Alo, Bhi, Blo,
                                  aRow0, bRow0, bLo, bHi, K, (it + 1) * 32, tid);
            cp_commit();
            cp_wait<1>();
        } else {
            cp_wait<0>();
        }
        __syncthreads();
        stage_compute<NP>(sb + (it & 1) * STAGE, acc, wm, wn, lane);
        __syncthreads();
    }
}

// ---------------------------------------------------------------------------
// standalone GEMM kernel. EPI: 1 = +bias+residual -> fp32 C
//                              2 = +bias+exact gelu -> split-bf16 (Chi/Clo)
// ---------------------------------------------------------------------------
template<int EPI, int BN>
__global__ void __launch_bounds__(256, 2) mma_gemm(
    const __nv_bfloat16* __restrict__ Ahi, const __nv_bfloat16* __restrict__ Alo,
    const __nv_bfloat16* __restrict__ Bhi, const __nv_bfloat16* __restrict__ Blo,
    const float* __restrict__ bias, const float* __restrict__ res,
    float* __restrict__ C, __nv_bfloat16* __restrict__ Chi,
    __nv_bfloat16* __restrict__ Clo, int M, int Nc, int K)
{
    extern __shared__ char smem[];
    constexpr int NP = BN / 32;
    float acc[2][BN/16][4];
    const int m0 = blockIdx.y * 128, n0 = blockIdx.x * BN;
    run_gemm<BN,false>(smem, acc, Ahi, Alo, Bhi, Blo, m0, n0, 0, 0x7fffffff, K);

    const int wid = threadIdx.x >> 5, lane = threadIdx.x & 31;
    const int wm = wid & 3, wn = wid >> 2;
    const int g = lane >> 2, tg = lane & 3;

    #pragma unroll
    for (int nt = 0; nt < BN/16; nt++) {
        const int col = n0 + wn * (NP * 16) + nt * 8 + 2 * tg;
        const float b0 = bias[col], b1 = bias[col + 1];
        #pragma unroll
        for (int mt = 0; mt < 2; mt++) {
            #pragma unroll
            for (int hr = 0; hr < 2; hr++) {
                const int row = m0 + wm * 32 + mt * 16 + g + hr * 8;
                float vx = acc[mt][nt][hr * 2 + 0] + b0;
                float vy = acc[mt][nt][hr * 2 + 1] + b1;
                if (EPI == 1) {
                    const float2 r2 = *(const float2*)(res + (size_t)row * Nc + col);
                    vx += r2.x; vy += r2.y;
                    float2 o; o.x = vx; o.y = vy;
                    *(float2*)(C + (size_t)row * Nc + col) = o;
                } else {
                    vx = 0.5f * vx * (1.0f + erff(vx * 0.70710678118654752f));
                    vy = 0.5f * vy * (1.0f + erff(vy * 0.70710678118654752f));
                    __nv_bfloat162 h2, l2;
                    split_bf16(vx, h2.x, l2.x);
                    split_bf16(vy, h2.y, l2.y);
                    *(__nv_bfloat162*)(Chi + (size_t)row * Nc + col) = h2;
                    *(__nv_bfloat162*)(Clo + (size_t)row * Nc + col) = l2;
                }
            }
        }
    }
}

// ---------------------------------------------------------------------------
// fused QKV projection + banded correlation, one launch.
// ---------------------------------------------------------------------------
__global__ void __launch_bounds__(256, 2) mma_qkv_corr(
    const __nv_bfloat16* __restrict__ Xhi, const __nv_bfloat16* __restrict__ Xlo,
    const __nv_bfloat16* __restrict__ Whi, const __nv_bfloat16* __restrict__ Wlo,
    const float* __restrict__ bias, float* __restrict__ Cqkv,
    const float* __restrict__ rn, float* __restrict__ corrT)
{
    extern __shared__ char smem[];
    const int wid = threadIdx.x >> 5, lane = threadIdx.x & 31;
    const int wm = wid & 3, wn = wid >> 2;
    const int g = lane >> 2, tg = lane & 3;

    if (blockIdx.x < 384) {
        float acc[2][8][4];
        const int n0 = (blockIdx.x % 12) * 128, m0 = (blockIdx.x / 12) * 128;
        run_gemm<128,false>(smem, acc, Xhi, Xlo, Whi, Wlo, m0, n0, 0, 0x7fffffff, D_);

        #pragma unroll
        for (int nt = 0; nt < 8; nt++) {
            const int col = n0 + wn * 64 + nt * 8 + 2 * tg;
            const float b0 = bias[col], b1 = bias[col + 1];
            #pragma unroll
            for (int mt = 0; mt < 2; mt++) {
                #pragma unroll
                for (int hr = 0; hr < 2; hr++) {
                    const int row = m0 + wm * 32 + mt * 16 + g + hr * 8;
                    float2 o;
                    o.x = acc[mt][nt][hr * 2 + 0] + b0;
                    o.y = acc[mt][nt][hr * 2 + 1] + b1;
                    *(float2*)(Cqkv + (size_t)row * (3 * D_) + col) = o;
                }
            }
        }
    } else {
        const int cid = blockIdx.x - 384;        // 0..63
        const int b = cid >> 5;
        const int t2 = cid & 31;
        const int bi = t2 >> 1, side = t2 & 1;
        const int m0 = bi * 128;
        const int n0 = m0 - 64 + side * 128;
        float acc[2][8][4];
        run_gemm<128,true>(smem, acc, Xhi, Xlo, Xhi, Xlo,
                           b * N_ + m0, b * N_ + n0, b * N_, b * N_ + N_, D_);

        #pragma unroll
        for (int mt = 0; mt < 2; mt++) {
            #pragma unroll
            for (int hr = 0; hr < 2; hr++) {
                const int gi = m0 + wm * 32 + mt * 16 + g + hr * 8;
                const float rni = rn[b * N_ + gi];
                #pragma unroll
                for (int nt = 0; nt < 8; nt++) {
                    #pragma unroll
                    for (int cc = 0; cc < 2; cc++) {
                        const int gj = n0 + wn * 64 + nt * 8 + 2 * tg + cc;
                        const int r = gi - gj;
                        if (r >= -R_ && r <= R_ && gj >= 0 && gj < N_)
                            corrT[(size_t)(b * N_ + gj) * BAND_ + (r + R_)] =
                                acc[mt][nt][hr * 2 + cc] * rni * rn[b * N_ + gj];
                    }
                }
            }
        }
    }
}

// ---------------------------------------------------------------------------
// LayerNorm -> split-bf16 directly (+ optional rep inverse-norm)
// ---------------------------------------------------------------------------
__global__ void __launch_bounds__(128) ln_split(
    const float* __restrict__ in, const float* __restrict__ gam,
    const float* __restrict__ bet, __nv_bfloat16* __restrict__ ohi,
    __nv_bfloat16* __restrict__ olo, float* __restrict__ rnorm)
{
    const int row = blockIdx.x;
    const int t = threadIdx.x;
    const float4 v = ((const float4*)(in + (size_t)row * D_))[t];

    float s  = v.x + v.y + v.z + v.w;
    float ss = v.x*v.x + v.y*v.y + v.z*v.z + v.w*v.w;
    __shared__ float redA[4], redB[4], redC[4];
    #pragma unroll
    for (int o = 16; o > 0; o >>= 1) {
        s  += __shfl_xor_sync(0xffffffffu, s,  o);
        ss += __shfl_xor_sync(0xffffffffu, ss, o);
    }
    const int w = t >> 5;
    if ((t & 31) == 0) { redA[w] = s; redB[w] = ss; }
    __syncthreads();
    s  = redA[0] + redA[1] + redA[2] + redA[3];
    ss = redB[0] + redB[1] + redB[2] + redB[3];

    const float mean = s * (1.0f / D_);
    const float var  = ss * (1.0f / D_) - mean * mean;
    const float rstd = rsqrtf(var + 1e-5f);

    const float4 gv = ((const float4*)gam)[t];
    const float4 bv = ((const float4*)bet)[t];
    float4 xo;
    xo.x = (v.x - mean) * rstd * gv.x + bv.x;
    xo.y = (v.y - mean) * rstd * gv.y + bv.y;
    xo.z = (v.z - mean) * rstd * gv.z + bv.z;
    xo.w = (v.w - mean) * rstd * gv.w + bv.w;

    __nv_bfloat162 h0, h1, l0, l1;
    split_bf16(xo.x, h0.x, l0.x);
    split_bf16(xo.y, h0.y, l0.y);
    split_bf16(xo.z, h1.x, l1.x);
    split_bf16(xo.w, h1.y, l1.y);
    ((__nv_bfloat162*)(ohi + (size_t)row * D_))[2*t]   = h0;
    ((__nv_bfloat162*)(ohi + (size_t)row * D_))[2*t+1] = h1;
    ((__nv_bfloat162*)(olo + (size_t)row * D_))[2*t]   = l0;
    ((__nv_bfloat162*)(olo + (size_t)row * D_))[2*t+1] = l1;

    if (rnorm != nullptr) {
        float q = xo.x*xo.x + xo.y*xo.y + xo.z*xo.z + xo.w*xo.w;
        #pragma unroll
        for (int o = 16; o > 0; o >>= 1) q += __shfl_xor_sync(0xffffffffu, q, o);
        if ((t & 31) == 0) redC[w] = q;
        __syncthreads();
        if (t == 0) {
            float tot = redC[0] + redC[1] + redC[2] + redC[3];
            rnorm[row] = 1.0f / fmaxf(sqrtf(tot), 1e-12f);
        }
    }
}

// ---------------------------------------------------------------------------
// fused weight transpose + split (one launch)
// ---------------------------------------------------------------------------
__global__ void __launch_bounds__(256) wtr_all(
    const float* __restrict__ w_qkv, const float* __restrict__ w_proj,
    const float* __restrict__ w_m1, const float* __restrict__ w_m2,
    __nv_bfloat16* __restrict__ Thi, __nv_bfloat16* __restrict__ Tlo)
{
    int bid = blockIdx.x;
    const float* W; int K, Nc, nx, off;
    if (bid < 768)       { W = w_qkv;  K = 512;  Nc = 1536; nx = 48; off = OFF_QKV; }
    else if (bid < 1024) { bid -= 768;  W = w_proj; K = 512;  Nc = 512;  nx = 16; off = OFF_PROJ; }
    else if (bid < 1536) { bid -= 1024; W = w_m1;   K = 512;  Nc = 1024; nx = 32; off = OFF_M1; }
    else                 { bid -= 1536; W = w_m2;   K = 1024; Nc = 512;  nx = 16; off = OFF_M2; }
    const int n0 = (bid % nx) * 32, k0 = (bid / nx) * 32;

    __shared__ float tile[32][33];
    const int tx = threadIdx.x & 31, ty = threadIdx.x >> 5;
    #pragma unroll
    for (int r = 0; r < 32; r += 8)
        tile[ty + r][tx] = W[(size_t)(k0 + ty + r) * Nc + n0 + tx];
    __syncthreads();
    #pragma unroll
    for (int r = 0; r < 32; r += 8) {
        const float v = tile[tx][ty + r];
        const __nv_bfloat16 h = __float2bfloat16(v);
        const size_t o = (size_t)off + (size_t)(n0 + ty + r) * K + k0 + tx;
        Thi[o] = h;
        Tlo[o] = __float2bfloat16(v - __bfloat162float(h));
    }
}

// ---------------------------------------------------------------------------
// banded attention: qtile=64, 128 threads (2 per query), grid 512 blocks.
// Key window [q0-64, q0+128) in 3 chunks of 64. Output split-bf16.
// ---------------------------------------------------------------------------
__global__ void __launch_bounds__(128) attn_k(
    const float* __restrict__ qkv, const float* __restrict__ corrT,
    const float* __restrict__ rel_bias, const float* __restrict__ rep_scale,
    __nv_bfloat16* __restrict__ uhi, __nv_bfloat16* __restrict__ ulo)
{
    const int qt = blockIdx.x, h = blockIdx.y, b = blockIdx.z;
    const int q0 = qt * 64;
    const int t  = threadIdx.x;
    const int qi = t >> 1;          // query within tile (0..63)
    const int hf = t & 1;           // head-dim half
    const int i  = q0 + qi;
    const float rs = rep_scale[h];

    __shared__ float Ks[64][64];
    __shared__ float Vs[64][64];
    __shared__ float bias_s[BAND_];
    for (int r = t; r < BAND_; r += 128)
        bias_s[r] = rel_bias[(size_t)(r - R_ + N_ - 1) * H_ + h];

    float4 q4[8];
    const float4* qp = (const float4*)(qkv + (size_t)(b * N_ + i) * (3 * D_)
                                       + h * HD_ + hf * 32);
    #pragma unroll
    for (int c = 0; c < 8; c++) q4[c] = qp[c];

    float m = -1e29f, l = 0.f;
    float4 a4[8];
    #pragma unroll
    for (int c = 0; c < 8; c++) a4[c] = make_float4(0.f, 0.f, 0.f, 0.f);

    const int j0 = q0 - 64;
    const int w = t >> 5;
    const int iw0 = q0 + w * 16;            // warp covers 16 queries
    const int jlo = max(0, iw0 - R_);
    const int jhi = min(N_ - 1, iw0 + 15 + R_);

    for (int cch = 0; cch < 3; cch++) {
        const int cbase = j0 + cch * 64;
        __syncthreads();
        for (int idx = t; idx < 64 * 16; idx += 128) {
            const int rrow = idx >> 4, c4 = idx & 15;
            const int j = cbase + rrow;
            float4 kv = make_float4(0.f, 0.f, 0.f, 0.f), vv = kv;
            if (j >= 0 && j < N_) {
                const float* base = qkv + (size_t)(b * N_ + j) * (3 * D_) + h * HD_;
                kv = *(const float4*)(base + D_     + c4 * 4);
                vv = *(const float4*)(base + 2 * D_ + c4 * 4);
            }
            ((float4*)&Ks[0][0])[idx] = kv;
            ((float4*)&Vs[0][0])[idx] = vv;
        }
        __syncthreads();

        const int lo = max(jlo, cbase), hi = min(jhi, cbase + 63);
        for (int jj = lo; jj <= hi; jj++) {
            const int kr = jj - cbase;
            const float4* kp = (const float4*)&Ks[kr][hf * 32];
            float s = 0.f;
            #pragma unroll
            for (int c = 0; c < 8; c++) {
                s = fmaf(q4[c].x, kp[c].x, s);
                s = fmaf(q4[c].y, kp[c].y, s);
                s = fmaf(q4[c].z, kp[c].z, s);
                s = fmaf(q4[c].w, kp[c].w, s);
            }
            s += __shfl_xor_sync(0xffffffffu, s, 1);
            const int r = i - jj;
            const int rc = min(max(r, -R_), R_);
            const float sv = s * 0.125f
                + corrT[(size_t)(b * N_ + jj) * BAND_ + rc + R_] * rs
                + bias_s[rc + R_];
            s = (r >= -R_ && r <= R_) ? sv : -1e30f;

            const float mn = fmaxf(m, s);
            if (mn > m) {
                const float sc = __expf(m - mn);
                l *= sc;
                #pragma unroll
                for (int c = 0; c < 8; c++) {
                    a4[c].x *= sc; a4[c].y *= sc; a4[c].z *= sc; a4[c].w *= sc;
                }
                m = mn;
            }
            const float p = __expf(s - m);
            l += p;
            const float4* vp = (const float4*)&Vs[kr][hf * 32];
            #pragma unroll
            for (int c = 0; c < 8; c++) {
                a4[c].x = fmaf(p, vp[c].x, a4[c].x);
                a4[c].y = fmaf(p, vp[c].y, a4[c].y);
                a4[c].z = fmaf(p, vp[c].z, a4[c].z);
                a4[c].w = fmaf(p, vp[c].w, a4[c].w);
            }
        }
    }

    const float inv = 1.0f / l;
    const size_t obase = (size_t)(b * N_ + i) * D_ + h * HD_ + hf * 32;
    #pragma unroll
    for (int c = 0; c < 8; c++) {
        __nv_bfloat162 h0, h1, l0, l1;
        split_bf16(a4[c].x * inv, h0.x, l0.x);
        split_bf16(a4[c].y * inv, h0.y, l0.y);
        split_bf16(a4[c].z * inv, h1.x, l1.x);
        split_bf16(a4[c].w * inv, h1.y, l1.y);
        ((__nv_bfloat162*)(uhi + obase))[2*c]   = h0;
        ((__nv_bfloat162*)(uhi + obase))[2*c+1] = h1;
        ((__nv_bfloat162*)(ulo + obase))[2*c]   = l0;
        ((__nv_bfloat162*)(ulo + obase))[2*c+1] = l1;
    }
}

// ---------------------------------------------------------------------------
// launcher
// ---------------------------------------------------------------------------
#define SMEM128 (2 * (2 * A_SZ + 2 * 128 * LDSB))   // 81920
#define SMEM64  (2 * (2 * A_SZ + 2 *  64 * LDSB))   // 61440

extern "C" void kernel_launch(void* const* d_in, const int* in_sizes, int n_in,
                              void* d_out, int out_size)
{
    const float* nodes  = (const float*)d_in[0];
    const float* ln1_g  = (const float*)d_in[1];
    const float* ln1_b  = (const float*)d_in[2];
    const float* qkv_w  = (const float*)d_in[3];
    const float* qkv_b  = (const float*)d_in[4];
    const float* proj_w = (const float*)d_in[5];
    const float* proj_b = (const float*)d_in[6];
    const float* rep_s  = (const float*)d_in[7];
    const float* rel_b  = (const float*)d_in[8];
    const float* ln2_g  = (const float*)d_in[9];
    const float* ln2_b  = (const float*)d_in[10];
    const float* mlp_w1 = (const float*)d_in[11];
    const float* mlp_b1 = (const float*)d_in[12];
    const float* mlp_w2 = (const float*)d_in[13];
    const float* mlp_b2 = (const float*)d_in[14];
    float* out = (float*)d_out;

    float *rn, *qkv, *corr, *n2;
    __nv_bfloat16 *ahi, *alo, *whi, *wlo;
    cudaGetSymbolAddress((void**)&rn,   g_rn);
    cudaGetSymbolAddress((void**)&qkv,  g_qkv);
    cudaGetSymbolAddress((void**)&corr, g_corr);
    cudaGetSymbolAddress((void**)&n2,   g_n2);
    cudaGetSymbolAddress((void**)&ahi,  g_act_hi);
    cudaGetSymbolAddress((void**)&alo,  g_act_lo);
    cudaGetSymbolAddress((void**)&whi,  g_wt_hi);
    cudaGetSymbolAddress((void**)&wlo,  g_wt_lo);

    __nv_bfloat16* hbhi = ahi + (size_t)BNROWS * D_;
    __nv_bfloat16* hblo = alo + (size_t)BNROWS * D_;

    cudaFuncSetAttribute(mma_qkv_corr,
        cudaFuncAttributeMaxDynamicSharedMemorySize, SMEM128);
    cudaFuncSetAttribute(mma_gemm<1,64>,
        cudaFuncAttributeMaxDynamicSharedMemorySize, SMEM64);
    cudaFuncSetAttribute(mma_gemm<2,128>,
        cudaFuncAttributeMaxDynamicSharedMemorySize, SMEM128);

    // 0) weight transposes + split
    wtr_all<<<2048, 256>>>(qkv_w, proj_w, mlp_w1, mlp_w2, whi, wlo);
    // 1) LN1 -> split bf16 + rep inverse-norm
    ln_split<<<BNROWS, 128>>>(nodes, ln1_g, ln1_b, ahi, alo, rn);
    // 2) fused QKV projection + banded correlation (448 blocks)
    mma_qkv_corr<<<448, 256, SMEM128>>>(
        ahi, alo, whi + OFF_QKV, wlo + OFF_QKV, qkv_b, qkv, rn, corr);
    // 3) banded attention -> split bf16 upd (512 blocks, 128 thr)
    attn_k<<<dim3(N_ / 64, H_, B_), 128>>>(qkv, corr, rel_b, rep_s, ahi, alo);
    // 4) output projection + residual -> n2 (BN=64, 256 blocks)
    mma_gemm<1,64><<<dim3(8, 32), 256, SMEM64>>>(
        ahi, alo, whi + OFF_PROJ, wlo + OFF_PROJ, proj_b, nodes, n2,
        nullptr, nullptr, BNROWS, D_, D_);
    // 5) LN2 -> split bf16
    ln_split<<<BNROWS, 128>>>(n2, ln2_g, ln2_b, ahi, alo, nullptr);
    // 6) MLP up + gelu -> split bf16 hb (BN=128, 256 blocks)
    mma_gemm<2,128><<<dim3(8, 32), 256, SMEM128>>>(
        ahi, alo, whi + OFF_M1, wlo + OFF_M1, mlp_b1, nullptr, nullptr,
        hbhi, hblo, BNROWS, 2 * D_, D_);
    // 7) MLP down + residual -> out (BN=64, 256 blocks, K=1024)
    mma_gemm<1,64><<<dim3(8, 32), 256, SMEM64>>>(
        hbhi, hblo, whi + OFF_M2, wlo + OFF_M2, mlp_b2, n2, out,
        nullptr, nullptr, BNROWS, D_, 2 * D_);
}